// round 2
// baseline (speedup 1.0000x reference)
#include <cuda_runtime.h>
#include <math.h>

// Problem constants
#define B_  2
#define L_  4096
#define D_  128
#define H_  4

// Scratch (allocation-free rule: __device__ globals)
__device__ float g_q[B_ * H_ * L_ * D_];
__device__ float g_k[B_ * H_ * L_ * D_];
__device__ float g_v[B_ * H_ * L_ * D_];
__device__ float g_ctx[B_ * H_ * L_ * D_];

// ---------------------------------------------------------------------------
// Kernel 1: QKV projections.  out[b,h,l,e] = sum_d x[b,l,d] * W[h*D+e, d]
// Treated as C[M=8192, N=512] = X[M,128] @ W^T, W row-major [512,128].
// grid = (M/64, N/64, 3), block = 256.  4x4 micro-tile, strided mapping.
// ---------------------------------------------------------------------------
__global__ __launch_bounds__(256) void qkv_kernel(
    const float* __restrict__ x,
    const float* __restrict__ Wq,
    const float* __restrict__ Wk,
    const float* __restrict__ Wv)
{
    __shared__ float Xs[64 * 33];
    __shared__ float Ws[64 * 33];

    const float* W   = (blockIdx.z == 0) ? Wq : ((blockIdx.z == 1) ? Wk : Wv);
    float*       out = (blockIdx.z == 0) ? g_q : ((blockIdx.z == 1) ? g_k : g_v);

    const int t  = threadIdx.x;
    const int m0 = blockIdx.x * 64;
    const int n0 = blockIdx.y * 64;
    const int r0 = t >> 4;    // 0..15, rows r0, r0+16, r0+32, r0+48
    const int c0 = t & 15;    // 0..15, cols c0, c0+16, c0+32, c0+48

    float acc[4][4];
#pragma unroll
    for (int i = 0; i < 4; i++)
#pragma unroll
        for (int j = 0; j < 4; j++) acc[i][j] = 0.f;

    for (int kk = 0; kk < D_; kk += 32) {
        __syncthreads();
        // Load X tile [64 x 32] and W tile [64 x 32], float4 coalesced.
        for (int i = t; i < 512; i += 256) {
            int row = i >> 3;
            int c4  = (i & 7) * 4;
            float4 xv = *(const float4*)(x + (size_t)(m0 + row) * D_ + kk + c4);
            Xs[row * 33 + c4 + 0] = xv.x;
            Xs[row * 33 + c4 + 1] = xv.y;
            Xs[row * 33 + c4 + 2] = xv.z;
            Xs[row * 33 + c4 + 3] = xv.w;
            float4 wv = *(const float4*)(W + (size_t)(n0 + row) * D_ + kk + c4);
            Ws[row * 33 + c4 + 0] = wv.x;
            Ws[row * 33 + c4 + 1] = wv.y;
            Ws[row * 33 + c4 + 2] = wv.z;
            Ws[row * 33 + c4 + 3] = wv.w;
        }
        __syncthreads();

#pragma unroll 8
        for (int k = 0; k < 32; k++) {
            float a[4], bb[4];
#pragma unroll
            for (int i = 0; i < 4; i++) a[i]  = Xs[(r0 + 16 * i) * 33 + k];
#pragma unroll
            for (int j = 0; j < 4; j++) bb[j] = Ws[(c0 + 16 * j) * 33 + k];
#pragma unroll
            for (int i = 0; i < 4; i++)
#pragma unroll
                for (int j = 0; j < 4; j++) acc[i][j] += a[i] * bb[j];
        }
    }

#pragma unroll
    for (int i = 0; i < 4; i++) {
        int m = m0 + r0 + 16 * i;
        int b = m >> 12;          // /4096
        int l = m & 4095;
#pragma unroll
        for (int j = 0; j < 4; j++) {
            int n = n0 + c0 + 16 * j;
            int h = n >> 7;       // /128
            int e = n & 127;
            out[(((size_t)b * H_ + h) * L_ + l) * D_ + e] = acc[i][j];
        }
    }
}

// ---------------------------------------------------------------------------
// Kernel 2: causal flash attention, fp32 SIMT.
// grid = (L/64, B*H), block = 256.  One CTA = 64 query rows of one (b,h).
// Online softmax; S kept in registers; P staged via smem for P@V.
// ---------------------------------------------------------------------------
#define RQ 132   // smem row stride (words) for Q/K/V tiles (16B-aligned, low-conflict)
#define RP 66    // smem row stride for P tile

__global__ __launch_bounds__(256) void attn_kernel()
{
    extern __shared__ float sm[];
    float* Qs = sm;               // 64*132
    float* Ks = Qs + 64 * RQ;     // 64*132
    float* Vs = Ks + 64 * RQ;     // 64*132
    float* Ps = Vs + 64 * RQ;     // 64*66

    const int t  = threadIdx.x;
    const int qt = (gridDim.x - 1) - blockIdx.x;   // heavy tiles first
    const int bh = blockIdx.y;

    const float* qg = g_q + ((size_t)bh * L_ + (size_t)qt * 64) * D_;
    const float* kg = g_k + (size_t)bh * L_ * D_;
    const float* vg = g_v + (size_t)bh * L_ * D_;

    // Load Q tile once: 64 x 128 floats = 2048 float4.
    for (int i = t; i < 2048; i += 256) {
        int row = i >> 5;
        int c4  = (i & 31) * 4;
        float4 v = *(const float4*)(qg + (size_t)row * D_ + c4);
        *(float4*)(Qs + row * RQ + c4) = v;
    }

    const int r0 = t >> 4;   // row group base (rows r0 + 16*i)
    const int c0 = t & 15;   // col group base (cols c0 + 16*j); also owns d-slice c0*8..+8

    float acc[4][8];
#pragma unroll
    for (int i = 0; i < 4; i++)
#pragma unroll
        for (int dd = 0; dd < 8; dd++) acc[i][dd] = 0.f;
    float m_r[4], l_r[4];
#pragma unroll
    for (int i = 0; i < 4; i++) { m_r[i] = -INFINITY; l_r[i] = 0.f; }

    for (int kt = 0; kt <= qt; ++kt) {
        __syncthreads();   // protect Ks/Vs reload and Ps reuse
        const float* kp = kg + (size_t)kt * 64 * D_;
        const float* vp = vg + (size_t)kt * 64 * D_;
        for (int i = t; i < 2048; i += 256) {
            int row = i >> 5;
            int c4  = (i & 31) * 4;
            *(float4*)(Ks + row * RQ + c4) = *(const float4*)(kp + (size_t)row * D_ + c4);
            *(float4*)(Vs + row * RQ + c4) = *(const float4*)(vp + (size_t)row * D_ + c4);
        }
        __syncthreads();

        // ---- S = Q K^T  (4x4 micro-tile per thread, strided) ----
        float s[4][4];
#pragma unroll
        for (int i = 0; i < 4; i++)
#pragma unroll
            for (int j = 0; j < 4; j++) s[i][j] = 0.f;

#pragma unroll 4
        for (int d = 0; d < D_; d += 4) {
            float4 qv[4], kv[4];
#pragma unroll
            for (int i = 0; i < 4; i++) qv[i] = *(const float4*)(Qs + (r0 + 16 * i) * RQ + d);
#pragma unroll
            for (int j = 0; j < 4; j++) kv[j] = *(const float4*)(Ks + (c0 + 16 * j) * RQ + d);
#pragma unroll
            for (int i = 0; i < 4; i++)
#pragma unroll
                for (int j = 0; j < 4; j++) {
                    s[i][j] += qv[i].x * kv[j].x;
                    s[i][j] += qv[i].y * kv[j].y;
                    s[i][j] += qv[i].z * kv[j].z;
                    s[i][j] += qv[i].w * kv[j].w;
                }
        }

        // ---- causal mask on the diagonal tile ----
        if (kt == qt) {
#pragma unroll
            for (int i = 0; i < 4; i++)
#pragma unroll
                for (int j = 0; j < 4; j++)
                    if (c0 + 16 * j > r0 + 16 * i) s[i][j] = -INFINITY;
        }

        // ---- online softmax (per-row across the 16-lane group) ----
#pragma unroll
        for (int i = 0; i < 4; i++) {
            float mx = fmaxf(fmaxf(s[i][0], s[i][1]), fmaxf(s[i][2], s[i][3]));
#pragma unroll
            for (int o = 8; o >= 1; o >>= 1)
                mx = fmaxf(mx, __shfl_xor_sync(0xffffffffu, mx, o));
            float mn    = fmaxf(m_r[i], mx);          // finite: col 0 always valid
            float scale = __expf(m_r[i] - mn);        // 0 when m_r was -inf
            float psum  = 0.f;
#pragma unroll
            for (int j = 0; j < 4; j++) {
                float p = __expf(s[i][j] - mn);
                Ps[(r0 + 16 * i) * RP + c0 + 16 * j] = p;
                psum += p;
            }
#pragma unroll
            for (int o = 8; o >= 1; o >>= 1)
                psum += __shfl_xor_sync(0xffffffffu, psum, o);
            l_r[i] = l_r[i] * scale + psum;
            m_r[i] = mn;
#pragma unroll
            for (int dd = 0; dd < 8; dd++) acc[i][dd] *= scale;
        }
        __syncthreads();   // Ps visible to all

        // ---- O += P @ V  (thread owns rows r0+16i, d-slice [c0*8, c0*8+8)) ----
#pragma unroll 4
        for (int jj = 0; jj < 64; ++jj) {
            float4 v0 = *(const float4*)(Vs + jj * RQ + c0 * 8);
            float4 v1 = *(const float4*)(Vs + jj * RQ + c0 * 8 + 4);
#pragma unroll
            for (int i = 0; i < 4; i++) {
                float p = Ps[(r0 + 16 * i) * RP + jj];
                acc[i][0] += p * v0.x;  acc[i][1] += p * v0.y;
                acc[i][2] += p * v0.z;  acc[i][3] += p * v0.w;
                acc[i][4] += p * v1.x;  acc[i][5] += p * v1.y;
                acc[i][6] += p * v1.z;  acc[i][7] += p * v1.w;
            }
        }
    }

    // ---- epilogue: normalize and write ctx[b,h,row,d] ----
#pragma unroll
    for (int i = 0; i < 4; i++) {
        float inv = 1.f / l_r[i];
        float* dst = g_ctx + ((size_t)bh * L_ + (size_t)qt * 64 + r0 + 16 * i) * D_ + c0 * 8;
        float4 o0, o1;
        o0.x = acc[i][0] * inv; o0.y = acc[i][1] * inv;
        o0.z = acc[i][2] * inv; o0.w = acc[i][3] * inv;
        o1.x = acc[i][4] * inv; o1.y = acc[i][5] * inv;
        o1.z = acc[i][6] * inv; o1.w = acc[i][7] * inv;
        *(float4*)(dst)     = o0;
        *(float4*)(dst + 4) = o1;
    }
}

// ---------------------------------------------------------------------------
// Kernel 3: output projection.  y[b,l,d] = sum_{h,e} ctx[b,h,l,e] * Wo[d, h*D+e]
// C[M=8192, N=128] = CTX_flat[M,512] @ Wo^T.  grid = (M/64, N/64), block 256.
// ---------------------------------------------------------------------------
__global__ __launch_bounds__(256) void wo_kernel(
    const float* __restrict__ Wo,
    float* __restrict__ y)
{
    __shared__ float As[64 * 33];
    __shared__ float Bs[64 * 33];

    const int t  = threadIdx.x;
    const int m0 = blockIdx.x * 64;
    const int n0 = blockIdx.y * 64;
    const int r0 = t >> 4;
    const int c0 = t & 15;

    float acc[4][4];
#pragma unroll
    for (int i = 0; i < 4; i++)
#pragma unroll
        for (int j = 0; j < 4; j++) acc[i][j] = 0.f;

    for (int kk = 0; kk < H_ * D_; kk += 32) {
        __syncthreads();
        for (int i = t; i < 512; i += 256) {
            int row = i >> 3;
            int c4  = (i & 7) * 4;
            // A: gather from ctx[b,h,l,e] where k = kk + c4 .. +3 (same h, contiguous e)
            int m = m0 + row;
            int b = m >> 12;
            int l = m & 4095;
            int k = kk + c4;
            int h = k >> 7;
            int e = k & 127;
            float4 av = *(const float4*)(g_ctx + (((size_t)b * H_ + h) * L_ + l) * D_ + e);
            As[row * 33 + c4 + 0] = av.x;
            As[row * 33 + c4 + 1] = av.y;
            As[row * 33 + c4 + 2] = av.z;
            As[row * 33 + c4 + 3] = av.w;
            // B: Wo row (n0+row), cols kk+c4 (row stride 512)
            float4 wv = *(const float4*)(Wo + (size_t)(n0 + row) * (H_ * D_) + kk + c4);
            Bs[row * 33 + c4 + 0] = wv.x;
            Bs[row * 33 + c4 + 1] = wv.y;
            Bs[row * 33 + c4 + 2] = wv.z;
            Bs[row * 33 + c4 + 3] = wv.w;
        }
        __syncthreads();

#pragma unroll 8
        for (int k = 0; k < 32; k++) {
            float a[4], bb[4];
#pragma unroll
            for (int i = 0; i < 4; i++) a[i]  = As[(r0 + 16 * i) * 33 + k];
#pragma unroll
            for (int j = 0; j < 4; j++) bb[j] = Bs[(c0 + 16 * j) * 33 + k];
#pragma unroll
            for (int i = 0; i < 4; i++)
#pragma unroll
                for (int j = 0; j < 4; j++) acc[i][j] += a[i] * bb[j];
        }
    }

#pragma unroll
    for (int i = 0; i < 4; i++) {
        int m = m0 + r0 + 16 * i;
#pragma unroll
        for (int j = 0; j < 4; j++) {
            int n = n0 + c0 + 16 * j;
            y[(size_t)m * D_ + n] = acc[i][j];
        }
    }
}

// ---------------------------------------------------------------------------
extern "C" void kernel_launch(void* const* d_in, const int* in_sizes, int n_in,
                              void* d_out, int out_size)
{
    const float* x  = (const float*)d_in[0];
    const float* Wq = (const float*)d_in[1];
    const float* Wk = (const float*)d_in[2];
    const float* Wv = (const float*)d_in[3];
    const float* Wo = (const float*)d_in[4];
    float* y = (float*)d_out;

    // Attention smem: (3*64*132 + 64*66) * 4 = 118,272 B (opt-in > 48 KB).
    const int attn_smem = (3 * 64 * RQ + 64 * RP) * (int)sizeof(float);
    cudaFuncSetAttribute(attn_kernel, cudaFuncAttributeMaxDynamicSharedMemorySize,
                         attn_smem);

    // 1) QKV projections
    {
        dim3 grid((B_ * L_) / 64, (H_ * D_) / 64, 3);
        qkv_kernel<<<grid, 256>>>(x, Wq, Wk, Wv);
    }
    // 2) Causal flash attention
    {
        dim3 grid(L_ / 64, B_ * H_);
        attn_kernel<<<grid, 256, attn_smem>>>();
    }
    // 3) Output projection
    {
        dim3 grid((B_ * L_) / 64, D_ / 64);
        wo_kernel<<<grid, 256>>>(Wo, y);
    }
}

// round 3
// speedup vs baseline: 2.3504x; 2.3504x over previous
#include <cuda_runtime.h>
#include <math.h>

// Problem constants
#define B_  2
#define L_  4096
#define D_  128
#define H_  4

// Scratch (allocation-free rule: __device__ globals)
__device__ float g_q[B_ * H_ * L_ * D_];
__device__ float g_k[B_ * H_ * L_ * D_];
__device__ float g_v[B_ * H_ * L_ * D_];
__device__ float g_ctx[B_ * H_ * L_ * D_];

// ---------------------------------------------------------------------------
// Kernel 1: QKV projections (unchanged from R1 — 110us, not the bottleneck).
// ---------------------------------------------------------------------------
__global__ __launch_bounds__(256) void qkv_kernel(
    const float* __restrict__ x,
    const float* __restrict__ Wq,
    const float* __restrict__ Wk,
    const float* __restrict__ Wv)
{
    __shared__ float Xs[64 * 33];
    __shared__ float Ws[64 * 33];

    const float* W   = (blockIdx.z == 0) ? Wq : ((blockIdx.z == 1) ? Wk : Wv);
    float*       out = (blockIdx.z == 0) ? g_q : ((blockIdx.z == 1) ? g_k : g_v);

    const int t  = threadIdx.x;
    const int m0 = blockIdx.x * 64;
    const int n0 = blockIdx.y * 64;
    const int r0 = t >> 4;
    const int c0 = t & 15;

    float acc[4][4];
#pragma unroll
    for (int i = 0; i < 4; i++)
#pragma unroll
        for (int j = 0; j < 4; j++) acc[i][j] = 0.f;

    for (int kk = 0; kk < D_; kk += 32) {
        __syncthreads();
        for (int i = t; i < 512; i += 256) {
            int row = i >> 3;
            int c4  = (i & 7) * 4;
            float4 xv = *(const float4*)(x + (size_t)(m0 + row) * D_ + kk + c4);
            Xs[row * 33 + c4 + 0] = xv.x;
            Xs[row * 33 + c4 + 1] = xv.y;
            Xs[row * 33 + c4 + 2] = xv.z;
            Xs[row * 33 + c4 + 3] = xv.w;
            float4 wv = *(const float4*)(W + (size_t)(n0 + row) * D_ + kk + c4);
            Ws[row * 33 + c4 + 0] = wv.x;
            Ws[row * 33 + c4 + 1] = wv.y;
            Ws[row * 33 + c4 + 2] = wv.z;
            Ws[row * 33 + c4 + 3] = wv.w;
        }
        __syncthreads();

#pragma unroll 8
        for (int k = 0; k < 32; k++) {
            float a[4], bb[4];
#pragma unroll
            for (int i = 0; i < 4; i++) a[i]  = Xs[(r0 + 16 * i) * 33 + k];
#pragma unroll
            for (int j = 0; j < 4; j++) bb[j] = Ws[(c0 + 16 * j) * 33 + k];
#pragma unroll
            for (int i = 0; i < 4; i++)
#pragma unroll
                for (int j = 0; j < 4; j++) acc[i][j] += a[i] * bb[j];
        }
    }

#pragma unroll
    for (int i = 0; i < 4; i++) {
        int m = m0 + r0 + 16 * i;
        int b = m >> 12;
        int l = m & 4095;
#pragma unroll
        for (int j = 0; j < 4; j++) {
            int n = n0 + c0 + 16 * j;
            int h = n >> 7;
            int e = n & 127;
            out[(((size_t)b * H_ + h) * L_ + l) * D_ + e] = acc[i][j];
        }
    }
}

// ---------------------------------------------------------------------------
// tf32 mma.sync helpers
// ---------------------------------------------------------------------------
__device__ __forceinline__ unsigned f2tf(float f) {
    unsigned r;
    asm("cvt.rna.tf32.f32 %0, %1;" : "=r"(r) : "f"(f));
    return r;
}

__device__ __forceinline__ void mma8(float d[4], const unsigned a[4],
                                     unsigned b0, unsigned b1) {
    asm volatile(
        "mma.sync.aligned.m16n8k8.row.col.f32.tf32.tf32.f32 "
        "{%0,%1,%2,%3}, {%4,%5,%6,%7}, {%8,%9}, {%0,%1,%2,%3};\n"
        : "+f"(d[0]), "+f"(d[1]), "+f"(d[2]), "+f"(d[3])
        : "r"(a[0]), "r"(a[1]), "r"(a[2]), "r"(a[3]), "r"(b0), "r"(b1));
}

// ---------------------------------------------------------------------------
// Kernel 2: causal flash attention, tf32 tensor cores.
// grid = (L/128, B*H), block = 256 (8 warps).  Warp w owns q rows [w*16,w*16+16).
// Key tiles of 64.  K row-major stride 132, V transposed stride 68, P stride 68.
// All fragment LDS patterns are bank-conflict-free (bank = 4*(l>>2)+(l&3)).
// ---------------------------------------------------------------------------
#define KSTR 132
#define VSTR 68
#define PSTR 68

__global__ __launch_bounds__(256, 1) void attn_kernel()
{
    extern __shared__ unsigned sm[];
    unsigned* Ks = sm;                 // 64  * 132 = 8448 words (tf32 bits)
    unsigned* Vt = Ks + 64 * KSTR;     // 128 * 68  = 8704 words (transposed)
    unsigned* Ps = Vt + 128 * VSTR;    // 128 * 68  = 8704 words

    const int t    = threadIdx.x;
    const int w    = t >> 5;
    const int lane = t & 31;
    const int rl   = lane >> 2;        // 0..7
    const int cl   = lane & 3;         // 0..3
    const int qt   = (gridDim.x - 1) - blockIdx.x;   // heavy tiles first
    const int bh   = blockIdx.y;

    const float* qg = g_q + ((size_t)bh * L_ + (size_t)qt * 128) * D_;
    const float* kg = g_k + (size_t)bh * L_ * D_;
    const float* vg = g_v + (size_t)bh * L_ * D_;

    // ---- Q A-fragments, cached in registers for the whole CTA lifetime ----
    unsigned Qa[16][4];
    {
        const float* qw = qg + (size_t)(w * 16) * D_;
#pragma unroll
        for (int kt = 0; kt < 16; kt++) {
            Qa[kt][0] = f2tf(qw[(size_t)(rl)     * D_ + kt * 8 + cl]);
            Qa[kt][1] = f2tf(qw[(size_t)(rl + 8) * D_ + kt * 8 + cl]);
            Qa[kt][2] = f2tf(qw[(size_t)(rl)     * D_ + kt * 8 + 4 + cl]);
            Qa[kt][3] = f2tf(qw[(size_t)(rl + 8) * D_ + kt * 8 + 4 + cl]);
        }
    }

    float Oacc[16][4];
#pragma unroll
    for (int nt = 0; nt < 16; nt++)
#pragma unroll
        for (int c = 0; c < 4; c++) Oacc[nt][c] = 0.f;
    float m0 = -INFINITY, m1 = -INFINITY, l0 = 0.f, l1 = 0.f;

    const int qg0 = qt * 128 + w * 16 + rl;   // global q row (low)
    const int qg1 = qg0 + 8;                  // global q row (high)
    const int ntiles = 2 * qt + 2;

    for (int kb = 0; kb < ntiles; ++kb) {
        __syncthreads();
        // ---- stage K (row-major) and V (transposed), converting to tf32 ----
        {
            const float* kp = kg + (size_t)kb * 64 * D_;
            const float* vp = vg + (size_t)kb * 64 * D_;
            for (int i = t; i < 2048; i += 256) {
                // K: coalesced rows, STS.128, conflict-free
                int row = i >> 5;
                int c4  = (i & 31) * 4;
                float4 kv = *(const float4*)(kp + (size_t)row * D_ + c4);
                uint4 ko;
                ko.x = f2tf(kv.x); ko.y = f2tf(kv.y);
                ko.z = f2tf(kv.z); ko.w = f2tf(kv.w);
                *(uint4*)(Ks + row * KSTR + c4) = ko;
                // V: key-fastest lanes (conflict-free scatter into Vt[d][key])
                int key = i & 63;
                int v4  = (i >> 6) * 4;
                float4 vv = *(const float4*)(vp + (size_t)key * D_ + v4);
                Vt[(v4 + 0) * VSTR + key] = f2tf(vv.x);
                Vt[(v4 + 1) * VSTR + key] = f2tf(vv.y);
                Vt[(v4 + 2) * VSTR + key] = f2tf(vv.z);
                Vt[(v4 + 3) * VSTR + key] = f2tf(vv.w);
            }
        }
        __syncthreads();

        // ---- S = Q K^T  (8 n-tiles of 8 keys; 128 HMMA per warp) ----
        float Sf[8][4];
#pragma unroll
        for (int nt = 0; nt < 8; nt++)
#pragma unroll
            for (int c = 0; c < 4; c++) Sf[nt][c] = 0.f;

#pragma unroll
        for (int kt = 0; kt < 16; kt++) {
#pragma unroll
            for (int nt = 0; nt < 8; nt++) {
                unsigned b0 = Ks[(nt * 8 + rl) * KSTR + kt * 8 + cl];
                unsigned b1 = Ks[(nt * 8 + rl) * KSTR + kt * 8 + 4 + cl];
                mma8(Sf[nt], Qa[kt], b0, b1);
            }
        }

        // ---- causal mask (only the last two tiles touch the diagonal) ----
        if (kb >= 2 * qt) {
#pragma unroll
            for (int nt = 0; nt < 8; nt++) {
                int kgb = kb * 64 + nt * 8 + 2 * cl;
                if (kgb     > qg0) Sf[nt][0] = -INFINITY;
                if (kgb + 1 > qg0) Sf[nt][1] = -INFINITY;
                if (kgb     > qg1) Sf[nt][2] = -INFINITY;
                if (kgb + 1 > qg1) Sf[nt][3] = -INFINITY;
            }
        }

        // ---- online softmax (4-lane row groups) ----
        float mx0 = Sf[0][0], mx1 = Sf[0][2];
#pragma unroll
        for (int nt = 0; nt < 8; nt++) {
            mx0 = fmaxf(mx0, fmaxf(Sf[nt][0], Sf[nt][1]));
            mx1 = fmaxf(mx1, fmaxf(Sf[nt][2], Sf[nt][3]));
        }
        mx0 = fmaxf(mx0, __shfl_xor_sync(0xffffffffu, mx0, 1));
        mx0 = fmaxf(mx0, __shfl_xor_sync(0xffffffffu, mx0, 2));
        mx1 = fmaxf(mx1, __shfl_xor_sync(0xffffffffu, mx1, 1));
        mx1 = fmaxf(mx1, __shfl_xor_sync(0xffffffffu, mx1, 2));

        float mn0 = fmaxf(m0, mx0);
        float mn1 = fmaxf(m1, mx1);
        float sc0 = __expf(m0 - mn0);
        float sc1 = __expf(m1 - mn1);
        m0 = mn0; m1 = mn1;

        float rs0 = 0.f, rs1 = 0.f;
        unsigned* prow0 = Ps + (w * 16 + rl)     * PSTR + 2 * cl;
        unsigned* prow1 = Ps + (w * 16 + 8 + rl) * PSTR + 2 * cl;
#pragma unroll
        for (int nt = 0; nt < 8; nt++) {
            float p0 = __expf(Sf[nt][0] - mn0);
            float p1 = __expf(Sf[nt][1] - mn0);
            float p2 = __expf(Sf[nt][2] - mn1);
            float p3 = __expf(Sf[nt][3] - mn1);
            rs0 += p0 + p1;
            rs1 += p2 + p3;
            uint2 w0; w0.x = f2tf(p0); w0.y = f2tf(p1);
            uint2 w1; w1.x = f2tf(p2); w1.y = f2tf(p3);
            *(uint2*)(prow0 + nt * 8) = w0;
            *(uint2*)(prow1 + nt * 8) = w1;
        }
        rs0 += __shfl_xor_sync(0xffffffffu, rs0, 1);
        rs0 += __shfl_xor_sync(0xffffffffu, rs0, 2);
        rs1 += __shfl_xor_sync(0xffffffffu, rs1, 1);
        rs1 += __shfl_xor_sync(0xffffffffu, rs1, 2);
        l0 = l0 * sc0 + rs0;
        l1 = l1 * sc1 + rs1;

#pragma unroll
        for (int nt = 0; nt < 16; nt++) {
            Oacc[nt][0] *= sc0; Oacc[nt][1] *= sc0;
            Oacc[nt][2] *= sc1; Oacc[nt][3] *= sc1;
        }
        __syncwarp();   // P visible within the warp (Ps region is warp-private)

        // ---- O += P V  (16 d-tiles; 128 HMMA per warp) ----
#pragma unroll
        for (int kt = 0; kt < 8; kt++) {
            unsigned Pa[4];
            Pa[0] = Ps[(w * 16 + rl)     * PSTR + kt * 8 + cl];
            Pa[1] = Ps[(w * 16 + 8 + rl) * PSTR + kt * 8 + cl];
            Pa[2] = Ps[(w * 16 + rl)     * PSTR + kt * 8 + 4 + cl];
            Pa[3] = Ps[(w * 16 + 8 + rl) * PSTR + kt * 8 + 4 + cl];
#pragma unroll
            for (int nt = 0; nt < 16; nt++) {
                unsigned b0 = Vt[(nt * 8 + rl) * VSTR + kt * 8 + cl];
                unsigned b1 = Vt[(nt * 8 + rl) * VSTR + kt * 8 + 4 + cl];
                mma8(Oacc[nt], Pa, b0, b1);
            }
        }
    }

    // ---- epilogue: normalize and write ctx ----
    float inv0 = 1.f / l0;
    float inv1 = 1.f / l1;
    float* dst0 = g_ctx + ((size_t)bh * L_ + (size_t)qt * 128 + w * 16 + rl)     * D_ + 2 * cl;
    float* dst1 = g_ctx + ((size_t)bh * L_ + (size_t)qt * 128 + w * 16 + 8 + rl) * D_ + 2 * cl;
#pragma unroll
    for (int nt = 0; nt < 16; nt++) {
        float2 o0; o0.x = Oacc[nt][0] * inv0; o0.y = Oacc[nt][1] * inv0;
        float2 o1; o1.x = Oacc[nt][2] * inv1; o1.y = Oacc[nt][3] * inv1;
        *(float2*)(dst0 + nt * 8) = o0;
        *(float2*)(dst1 + nt * 8) = o1;
    }
}

// ---------------------------------------------------------------------------
// Kernel 3: output projection (unchanged from R1).
// ---------------------------------------------------------------------------
__global__ __launch_bounds__(256) void wo_kernel(
    const float* __restrict__ Wo,
    float* __restrict__ y)
{
    __shared__ float As[64 * 33];
    __shared__ float Bs[64 * 33];

    const int t  = threadIdx.x;
    const int m0 = blockIdx.x * 64;
    const int n0 = blockIdx.y * 64;
    const int r0 = t >> 4;
    const int c0 = t & 15;

    float acc[4][4];
#pragma unroll
    for (int i = 0; i < 4; i++)
#pragma unroll
        for (int j = 0; j < 4; j++) acc[i][j] = 0.f;

    for (int kk = 0; kk < H_ * D_; kk += 32) {
        __syncthreads();
        for (int i = t; i < 512; i += 256) {
            int row = i >> 3;
            int c4  = (i & 7) * 4;
            int m = m0 + row;
            int b = m >> 12;
            int l = m & 4095;
            int k = kk + c4;
            int h = k >> 7;
            int e = k & 127;
            float4 av = *(const float4*)(g_ctx + (((size_t)b * H_ + h) * L_ + l) * D_ + e);
            As[row * 33 + c4 + 0] = av.x;
            As[row * 33 + c4 + 1] = av.y;
            As[row * 33 + c4 + 2] = av.z;
            As[row * 33 + c4 + 3] = av.w;
            float4 wv = *(const float4*)(Wo + (size_t)(n0 + row) * (H_ * D_) + kk + c4);
            Bs[row * 33 + c4 + 0] = wv.x;
            Bs[row * 33 + c4 + 1] = wv.y;
            Bs[row * 33 + c4 + 2] = wv.z;
            Bs[row * 33 + c4 + 3] = wv.w;
        }
        __syncthreads();

#pragma unroll 8
        for (int k = 0; k < 32; k++) {
            float a[4], bb[4];
#pragma unroll
            for (int i = 0; i < 4; i++) a[i]  = As[(r0 + 16 * i) * 33 + k];
#pragma unroll
            for (int j = 0; j < 4; j++) bb[j] = Bs[(c0 + 16 * j) * 33 + k];
#pragma unroll
            for (int i = 0; i < 4; i++)
#pragma unroll
                for (int j = 0; j < 4; j++) acc[i][j] += a[i] * bb[j];
        }
    }

#pragma unroll
    for (int i = 0; i < 4; i++) {
        int m = m0 + r0 + 16 * i;
#pragma unroll
        for (int j = 0; j < 4; j++) {
            int n = n0 + c0 + 16 * j;
            y[(size_t)m * D_ + n] = acc[i][j];
        }
    }
}

// ---------------------------------------------------------------------------
extern "C" void kernel_launch(void* const* d_in, const int* in_sizes, int n_in,
                              void* d_out, int out_size)
{
    const float* x  = (const float*)d_in[0];
    const float* Wq = (const float*)d_in[1];
    const float* Wk = (const float*)d_in[2];
    const float* Wv = (const float*)d_in[3];
    const float* Wo = (const float*)d_in[4];
    float* y = (float*)d_out;

    // attn smem: (64*132 + 128*68 + 128*68) * 4 = 103,424 B
    const int attn_smem = (64 * KSTR + 128 * VSTR + 128 * PSTR) * (int)sizeof(unsigned);
    cudaFuncSetAttribute(attn_kernel, cudaFuncAttributeMaxDynamicSharedMemorySize,
                         attn_smem);

    // 1) QKV projections
    {
        dim3 grid((B_ * L_) / 64, (H_ * D_) / 64, 3);
        qkv_kernel<<<grid, 256>>>(x, Wq, Wk, Wv);
    }
    // 2) Causal flash attention (tf32 tensor cores)
    {
        dim3 grid(L_ / 128, B_ * H_);
        attn_kernel<<<grid, 256, attn_smem>>>();
    }
    // 3) Output projection
    {
        dim3 grid((B_ * L_) / 64, D_ / 64);
        wo_kernel<<<grid, 256>>>(Wo, y);
    }
}

// round 6
// speedup vs baseline: 2.3526x; 1.0009x over previous
#include <cuda_runtime.h>
#include <math.h>

// Problem constants
#define B_  2
#define L_  4096
#define D_  128
#define H_  4

// Scratch (allocation-free rule: __device__ globals)
__device__ float g_q[B_ * H_ * L_ * D_];
__device__ float g_k[B_ * H_ * L_ * D_];
__device__ float g_v[B_ * H_ * L_ * D_];
__device__ float g_ctx[B_ * L_ * H_ * D_];   // [b][l][h][e]  (row-major [8192][512])

// ---------------------------------------------------------------------------
// tf32 helpers
// ---------------------------------------------------------------------------
__device__ __forceinline__ unsigned f2tf(float f) {
    unsigned r;
    asm("cvt.rna.tf32.f32 %0, %1;" : "=r"(r) : "f"(f));
    return r;
}

__device__ __forceinline__ void mma8(float d[4], const unsigned a[4],
                                     unsigned b0, unsigned b1) {
    asm volatile(
        "mma.sync.aligned.m16n8k8.row.col.f32.tf32.tf32.f32 "
        "{%0,%1,%2,%3}, {%4,%5,%6,%7}, {%8,%9}, {%0,%1,%2,%3};\n"
        : "+f"(d[0]), "+f"(d[1]), "+f"(d[2]), "+f"(d[3])
        : "r"(a[0]), "r"(a[1]), "r"(a[2]), "r"(a[3]), "r"(b0), "r"(b1));
}

// Fragment-major column permutations.
// For a row of C columns, element c = kt*8 + p (p = 0..7) goes to:
//   pi_128(c) = (c>>6)*64 + ((c>>2)&1)*32 + (c&3)*8 + ((c>>3)&7)     (C=128)
//   pi_64 (c) = ((c>>2)&1)*32 + (c&3)*8 + (c>>3)                     (C=64)
// Then the B/A fragment regs for 4 consecutive kt steps are one LDS.128:
//   b0[kt..kt+3] at row*STR + (kt>>3)*64 + (kt&7) + cl*8  (b1 at +32)

// ---------------------------------------------------------------------------
// Kernel 1: QKV projections, tf32 tensor cores.
// C[8192,512] = X[8192,128] @ W^T.  CTA tile 128x128, 8 warps (4m x 2n),
// warp tile 32x64.  grid = (64, 4, 3).
// ---------------------------------------------------------------------------
#define GSTR 132   // pi_128 row stride (mod 32 == 4)

__global__ __launch_bounds__(256) void qkv_kernel(
    const float* __restrict__ x,
    const float* __restrict__ Wq,
    const float* __restrict__ Wk,
    const float* __restrict__ Wv)
{
    extern __shared__ unsigned gsm[];
    unsigned* As = gsm;                // 128 * 132
    unsigned* Bs = As + 128 * GSTR;    // 128 * 132

    const float* W   = (blockIdx.z == 0) ? Wq : ((blockIdx.z == 1) ? Wk : Wv);
    float*       out = (blockIdx.z == 0) ? g_q : ((blockIdx.z == 1) ? g_k : g_v);

    const int t    = threadIdx.x;
    const int w    = t >> 5;
    const int lane = t & 31;
    const int rl   = lane >> 2;
    const int cl   = lane & 3;
    const int wm   = w & 3;            // m-warp 0..3
    const int wn   = w >> 2;           // n-warp 0..1
    const int m0   = blockIdx.x * 128;
    const int n0   = blockIdx.y * 128;

    // ---- stage X and W tiles, pi_128-permuted tf32 ----
    for (int i = t; i < 4096; i += 256) {
        int row = i >> 5;
        int c4  = (i & 31) * 4;
        int base = row * GSTR + ((c4 >> 6) << 6) + (((c4 >> 2) & 1) << 5) + ((c4 >> 3) & 7);
        float4 xv = *(const float4*)(x + (size_t)(m0 + row) * D_ + c4);
        As[base]      = f2tf(xv.x);
        As[base + 8]  = f2tf(xv.y);
        As[base + 16] = f2tf(xv.z);
        As[base + 24] = f2tf(xv.w);
        float4 wv = *(const float4*)(W + (size_t)(n0 + row) * D_ + c4);
        Bs[base]      = f2tf(wv.x);
        Bs[base + 8]  = f2tf(wv.y);
        Bs[base + 16] = f2tf(wv.z);
        Bs[base + 24] = f2tf(wv.w);
    }
    __syncthreads();

    float acc[2][8][4];
#pragma unroll
    for (int mt = 0; mt < 2; mt++)
#pragma unroll
        for (int nt = 0; nt < 8; nt++)
#pragma unroll
            for (int c = 0; c < 4; c++) acc[mt][nt][c] = 0.f;

#pragma unroll
    for (int ktg = 0; ktg < 4; ktg++) {   // kt = ktg*4 + u
        const int kbase = ((ktg >> 1) << 6) + ((ktg & 1) << 2) + cl * 8;
        uint4 a0[2], a1[2], a2[2], a3[2];
#pragma unroll
        for (int mt = 0; mt < 2; mt++) {
            int ar = (wm * 32 + mt * 16 + rl) * GSTR + kbase;
            a0[mt] = *(const uint4*)&As[ar];
            a2[mt] = *(const uint4*)&As[ar + 32];
            a1[mt] = *(const uint4*)&As[ar + 8 * GSTR];
            a3[mt] = *(const uint4*)&As[ar + 8 * GSTR + 32];
        }
#pragma unroll
        for (int nt = 0; nt < 8; nt++) {
            int br = (wn * 64 + nt * 8 + rl) * GSTR + kbase;
            uint4 b0 = *(const uint4*)&Bs[br];
            uint4 b1 = *(const uint4*)&Bs[br + 32];
#pragma unroll
            for (int mt = 0; mt < 2; mt++) {
                unsigned aa[4];
                aa[0] = a0[mt].x; aa[1] = a1[mt].x; aa[2] = a2[mt].x; aa[3] = a3[mt].x;
                mma8(acc[mt][nt], aa, b0.x, b1.x);
                aa[0] = a0[mt].y; aa[1] = a1[mt].y; aa[2] = a2[mt].y; aa[3] = a3[mt].y;
                mma8(acc[mt][nt], aa, b0.y, b1.y);
                aa[0] = a0[mt].z; aa[1] = a1[mt].z; aa[2] = a2[mt].z; aa[3] = a3[mt].z;
                mma8(acc[mt][nt], aa, b0.z, b1.z);
                aa[0] = a0[mt].w; aa[1] = a1[mt].w; aa[2] = a2[mt].w; aa[3] = a3[mt].w;
                mma8(acc[mt][nt], aa, b0.w, b1.w);
            }
        }
    }

    // ---- epilogue: out[b][h][l][e] ----
#pragma unroll
    for (int mt = 0; mt < 2; mt++) {
        int m = m0 + wm * 32 + mt * 16 + rl;
        int b = m >> 12;
        int l = m & 4095;
#pragma unroll
        for (int nt = 0; nt < 8; nt++) {
            int n = n0 + wn * 64 + nt * 8 + 2 * cl;
            int h = n >> 7;
            int e = n & 127;
            float* dst = out + (((size_t)b * H_ + h) * L_ + l) * D_ + e;
            float2 lo; lo.x = acc[mt][nt][0]; lo.y = acc[mt][nt][1];
            float2 hi; hi.x = acc[mt][nt][2]; hi.y = acc[mt][nt][3];
            *(float2*)dst = lo;
            *(float2*)(dst + 8 * (size_t)D_) = hi;
        }
    }
}

// ---------------------------------------------------------------------------
// Kernel 2: causal flash attention, tf32, fragment-major smem layouts.
// grid = (L/128, B*H), block = 256 (8 warps; warp owns 16 q rows).
// ---------------------------------------------------------------------------
#define KSTR 132   // Ks: 64 rows (keys) x pi_128 cols (d)
#define VSTR 68    // Vt: 128 rows (d)  x pi_64 cols (keys)
#define PSTR 68    // Ps: 128 rows (q)  x pi_64 cols (keys)

__global__ __launch_bounds__(256, 1) void attn_kernel()
{
    extern __shared__ unsigned sm[];
    unsigned* Ks = sm;                 // 64  * 132
    unsigned* Vt = Ks + 64 * KSTR;     // 128 * 68
    unsigned* Ps = Vt + 128 * VSTR;    // 128 * 68

    const int t    = threadIdx.x;
    const int w    = t >> 5;
    const int lane = t & 31;
    const int rl   = lane >> 2;
    const int cl   = lane & 3;
    const int qt   = (gridDim.x - 1) - blockIdx.x;   // heavy tiles first
    const int bh   = blockIdx.y;

    const float* qg = g_q + ((size_t)bh * L_ + (size_t)qt * 128) * D_;
    const float* kg = g_k + (size_t)bh * L_ * D_;
    const float* vg = g_v + (size_t)bh * L_ * D_;

    // ---- Q A-fragments cached in registers ----
    unsigned Qa[16][4];
    {
        const float* qw = qg + (size_t)(w * 16) * D_;
#pragma unroll
        for (int kt = 0; kt < 16; kt++) {
            Qa[kt][0] = f2tf(qw[(size_t)(rl)     * D_ + kt * 8 + cl]);
            Qa[kt][1] = f2tf(qw[(size_t)(rl + 8) * D_ + kt * 8 + cl]);
            Qa[kt][2] = f2tf(qw[(size_t)(rl)     * D_ + kt * 8 + 4 + cl]);
            Qa[kt][3] = f2tf(qw[(size_t)(rl + 8) * D_ + kt * 8 + 4 + cl]);
        }
    }

    float Oacc[16][4];
#pragma unroll
    for (int nt = 0; nt < 16; nt++)
#pragma unroll
        for (int c = 0; c < 4; c++) Oacc[nt][c] = 0.f;
    float m0 = -INFINITY, m1 = -INFINITY, l0 = 0.f, l1 = 0.f;

    const int qg0 = qt * 128 + w * 16 + rl;
    const int qg1 = qg0 + 8;
    const int ntiles = 2 * qt + 2;

    for (int kb = 0; kb < ntiles; ++kb) {
        __syncthreads();
        // ---- stage K (pi_128) and V (transposed, pi_64) as tf32 ----
        {
            const float* kp = kg + (size_t)kb * 64 * D_;
            const float* vp = vg + (size_t)kb * 64 * D_;
            for (int i = t; i < 2048; i += 256) {
                int row = i >> 5;
                int c4  = (i & 31) * 4;
                float4 kv = *(const float4*)(kp + (size_t)row * D_ + c4);
                int kbse = row * KSTR + ((c4 >> 6) << 6) + (((c4 >> 2) & 1) << 5) + ((c4 >> 3) & 7);
                Ks[kbse]      = f2tf(kv.x);
                Ks[kbse + 8]  = f2tf(kv.y);
                Ks[kbse + 16] = f2tf(kv.z);
                Ks[kbse + 24] = f2tf(kv.w);
                int key = i & 63;
                int v4  = (i >> 6) * 4;
                float4 vv = *(const float4*)(vp + (size_t)key * D_ + v4);
                int pc = (((key >> 2) & 1) << 5) + ((key & 3) << 3) + (key >> 3);
                Vt[(v4 + 0) * VSTR + pc] = f2tf(vv.x);
                Vt[(v4 + 1) * VSTR + pc] = f2tf(vv.y);
                Vt[(v4 + 2) * VSTR + pc] = f2tf(vv.z);
                Vt[(v4 + 3) * VSTR + pc] = f2tf(vv.w);
            }
        }
        __syncthreads();

        // ---- S = Q K^T : per ktg, one LDS.128 pair yields 4 kt-step B-frags ----
        float Sf[8][4];
#pragma unroll
        for (int nt = 0; nt < 8; nt++)
#pragma unroll
            for (int c = 0; c < 4; c++) Sf[nt][c] = 0.f;

#pragma unroll
        for (int ktg = 0; ktg < 4; ktg++) {
            const int kbase = ((ktg >> 1) << 6) + ((ktg & 1) << 2) + cl * 8;
#pragma unroll
            for (int nt = 0; nt < 8; nt++) {
                int br = (nt * 8 + rl) * KSTR + kbase;
                uint4 b0 = *(const uint4*)&Ks[br];
                uint4 b1 = *(const uint4*)&Ks[br + 32];
                mma8(Sf[nt], Qa[ktg * 4 + 0], b0.x, b1.x);
                mma8(Sf[nt], Qa[ktg * 4 + 1], b0.y, b1.y);
                mma8(Sf[nt], Qa[ktg * 4 + 2], b0.z, b1.z);
                mma8(Sf[nt], Qa[ktg * 4 + 3], b0.w, b1.w);
            }
        }

        // ---- causal mask (diagonal tiles only) ----
        if (kb >= 2 * qt) {
#pragma unroll
            for (int nt = 0; nt < 8; nt++) {
                int kgb = kb * 64 + nt * 8 + 2 * cl;
                if (kgb     > qg0) Sf[nt][0] = -INFINITY;
                if (kgb + 1 > qg0) Sf[nt][1] = -INFINITY;
                if (kgb     > qg1) Sf[nt][2] = -INFINITY;
                if (kgb + 1 > qg1) Sf[nt][3] = -INFINITY;
            }
        }

        // ---- online softmax; write P in pi_64 fragment-major layout ----
        float mx0 = Sf[0][0], mx1 = Sf[0][2];
#pragma unroll
        for (int nt = 0; nt < 8; nt++) {
            mx0 = fmaxf(mx0, fmaxf(Sf[nt][0], Sf[nt][1]));
            mx1 = fmaxf(mx1, fmaxf(Sf[nt][2], Sf[nt][3]));
        }
        mx0 = fmaxf(mx0, __shfl_xor_sync(0xffffffffu, mx0, 1));
        mx0 = fmaxf(mx0, __shfl_xor_sync(0xffffffffu, mx0, 2));
        mx1 = fmaxf(mx1, __shfl_xor_sync(0xffffffffu, mx1, 1));
        mx1 = fmaxf(mx1, __shfl_xor_sync(0xffffffffu, mx1, 2));

        float mn0 = fmaxf(m0, mx0);
        float mn1 = fmaxf(m1, mx1);
        float sc0 = __expf(m0 - mn0);
        float sc1 = __expf(m1 - mn1);
        m0 = mn0; m1 = mn1;

        float rs0 = 0.f, rs1 = 0.f;
        unsigned* prow0 = Ps + (w * 16 + rl)     * PSTR + cl * 16;
        unsigned* prow1 = Ps + (w * 16 + 8 + rl) * PSTR + cl * 16;
#pragma unroll
        for (int nt = 0; nt < 8; nt++) {
            float p0 = __expf(Sf[nt][0] - mn0);
            float p1 = __expf(Sf[nt][1] - mn0);
            float p2 = __expf(Sf[nt][2] - mn1);
            float p3 = __expf(Sf[nt][3] - mn1);
            rs0 += p0 + p1;
            rs1 += p2 + p3;
            prow0[nt]     = f2tf(p0);
            prow0[nt + 8] = f2tf(p1);
            prow1[nt]     = f2tf(p2);
            prow1[nt + 8] = f2tf(p3);
        }
        rs0 += __shfl_xor_sync(0xffffffffu, rs0, 1);
        rs0 += __shfl_xor_sync(0xffffffffu, rs0, 2);
        rs1 += __shfl_xor_sync(0xffffffffu, rs1, 1);
        rs1 += __shfl_xor_sync(0xffffffffu, rs1, 2);
        l0 = l0 * sc0 + rs0;
        l1 = l1 * sc1 + rs1;

#pragma unroll
        for (int nt = 0; nt < 16; nt++) {
            Oacc[nt][0] *= sc0; Oacc[nt][1] *= sc0;
            Oacc[nt][2] *= sc1; Oacc[nt][3] *= sc1;
        }
        __syncwarp();   // Ps region is warp-private

        // ---- O += P V : vectorized A and B fragment loads ----
#pragma unroll
        for (int ktg = 0; ktg < 2; ktg++) {
            int pb = (w * 16 + rl) * PSTR + cl * 8 + ktg * 4;
            uint4 a0 = *(const uint4*)&Ps[pb];
            uint4 a2 = *(const uint4*)&Ps[pb + 32];
            uint4 a1 = *(const uint4*)&Ps[pb + 8 * PSTR];
            uint4 a3 = *(const uint4*)&Ps[pb + 8 * PSTR + 32];
#pragma unroll
            for (int nt = 0; nt < 16; nt++) {
                int vb = (nt * 8 + rl) * VSTR + cl * 8 + ktg * 4;
                uint4 b0 = *(const uint4*)&Vt[vb];
                uint4 b1 = *(const uint4*)&Vt[vb + 32];
                unsigned aa[4];
                aa[0] = a0.x; aa[1] = a1.x; aa[2] = a2.x; aa[3] = a3.x;
                mma8(Oacc[nt], aa, b0.x, b1.x);
                aa[0] = a0.y; aa[1] = a1.y; aa[2] = a2.y; aa[3] = a3.y;
                mma8(Oacc[nt], aa, b0.y, b1.y);
                aa[0] = a0.z; aa[1] = a1.z; aa[2] = a2.z; aa[3] = a3.z;
                mma8(Oacc[nt], aa, b0.z, b1.z);
                aa[0] = a0.w; aa[1] = a1.w; aa[2] = a2.w; aa[3] = a3.w;
                mma8(Oacc[nt], aa, b0.w, b1.w);
            }
        }
    }

    // ---- epilogue: normalize, write ctx[b][l][h][e] ----
    float inv0 = 1.f / l0;
    float inv1 = 1.f / l1;
    const int b = bh >> 2;
    const int h = bh & 3;
    float* dst0 = g_ctx + ((size_t)(b * L_ + qt * 128 + w * 16 + rl))     * (H_ * D_) + h * D_ + 2 * cl;
    float* dst1 = g_ctx + ((size_t)(b * L_ + qt * 128 + w * 16 + 8 + rl)) * (H_ * D_) + h * D_ + 2 * cl;
#pragma unroll
    for (int nt = 0; nt < 16; nt++) {
        float2 o0; o0.x = Oacc[nt][0] * inv0; o0.y = Oacc[nt][1] * inv0;
        float2 o1; o1.x = Oacc[nt][2] * inv1; o1.y = Oacc[nt][3] * inv1;
        *(float2*)(dst0 + nt * 8) = o0;
        *(float2*)(dst1 + nt * 8) = o1;
    }
}

// ---------------------------------------------------------------------------
// Kernel 3: output projection, tf32 tensor cores.
// y[8192,128] = CTX[8192,512] @ Wo^T.  CTA tile 128x128, K chunked by 128.
// grid = (64).
// ---------------------------------------------------------------------------
__global__ __launch_bounds__(256) void wo_kernel(
    const float* __restrict__ Wo,
    float* __restrict__ y)
{
    extern __shared__ unsigned gsm[];
    unsigned* As = gsm;
    unsigned* Bs = As + 128 * GSTR;

    const int t    = threadIdx.x;
    const int w    = t >> 5;
    const int lane = t & 31;
    const int rl   = lane >> 2;
    const int cl   = lane & 3;
    const int wm   = w & 3;
    const int wn   = w >> 2;
    const int m0   = blockIdx.x * 128;

    float acc[2][8][4];
#pragma unroll
    for (int mt = 0; mt < 2; mt++)
#pragma unroll
        for (int nt = 0; nt < 8; nt++)
#pragma unroll
            for (int c = 0; c < 4; c++) acc[mt][nt][c] = 0.f;

    for (int kc = 0; kc < H_ * D_; kc += 128) {
        __syncthreads();
        for (int i = t; i < 4096; i += 256) {
            int row = i >> 5;
            int c4  = (i & 31) * 4;
            int base = row * GSTR + ((c4 >> 6) << 6) + (((c4 >> 2) & 1) << 5) + ((c4 >> 3) & 7);
            float4 av = *(const float4*)(g_ctx + (size_t)(m0 + row) * (H_ * D_) + kc + c4);
            As[base]      = f2tf(av.x);
            As[base + 8]  = f2tf(av.y);
            As[base + 16] = f2tf(av.z);
            As[base + 24] = f2tf(av.w);
            float4 wv = *(const float4*)(Wo + (size_t)row * (H_ * D_) + kc + c4);
            Bs[base]      = f2tf(wv.x);
            Bs[base + 8]  = f2tf(wv.y);
            Bs[base + 16] = f2tf(wv.z);
            Bs[base + 24] = f2tf(wv.w);
        }
        __syncthreads();

#pragma unroll
        for (int ktg = 0; ktg < 4; ktg++) {
            const int kbase = ((ktg >> 1) << 6) + ((ktg & 1) << 2) + cl * 8;
            uint4 a0[2], a1[2], a2[2], a3[2];
#pragma unroll
            for (int mt = 0; mt < 2; mt++) {
                int ar = (wm * 32 + mt * 16 + rl) * GSTR + kbase;
                a0[mt] = *(const uint4*)&As[ar];
                a2[mt] = *(const uint4*)&As[ar + 32];
                a1[mt] = *(const uint4*)&As[ar + 8 * GSTR];
                a3[mt] = *(const uint4*)&As[ar + 8 * GSTR + 32];
            }
#pragma unroll
            for (int nt = 0; nt < 8; nt++) {
                int br = (wn * 64 + nt * 8 + rl) * GSTR + kbase;
                uint4 b0 = *(const uint4*)&Bs[br];
                uint4 b1 = *(const uint4*)&Bs[br + 32];
#pragma unroll
                for (int mt = 0; mt < 2; mt++) {
                    unsigned aa[4];
                    aa[0] = a0[mt].x; aa[1] = a1[mt].x; aa[2] = a2[mt].x; aa[3] = a3[mt].x;
                    mma8(acc[mt][nt], aa, b0.x, b1.x);
                    aa[0] = a0[mt].y; aa[1] = a1[mt].y; aa[2] = a2[mt].y; aa[3] = a3[mt].y;
                    mma8(acc[mt][nt], aa, b0.y, b1.y);
                    aa[0] = a0[mt].z; aa[1] = a1[mt].z; aa[2] = a2[mt].z; aa[3] = a3[mt].z;
                    mma8(acc[mt][nt], aa, b0.z, b1.z);
                    aa[0] = a0[mt].w; aa[1] = a1[mt].w; aa[2] = a2[mt].w; aa[3] = a3[mt].w;
                    mma8(acc[mt][nt], aa, b0.w, b1.w);
                }
            }
        }
    }

#pragma unroll
    for (int mt = 0; mt < 2; mt++) {
        int m = m0 + wm * 32 + mt * 16 + rl;
#pragma unroll
        for (int nt = 0; nt < 8; nt++) {
            int n = wn * 64 + nt * 8 + 2 * cl;
            float* dst = y + (size_t)m * D_ + n;
            float2 lo; lo.x = acc[mt][nt][0]; lo.y = acc[mt][nt][1];
            float2 hi; hi.x = acc[mt][nt][2]; hi.y = acc[mt][nt][3];
            *(float2*)dst = lo;
            *(float2*)(dst + 8 * (size_t)D_) = hi;
        }
    }
}

// ---------------------------------------------------------------------------
extern "C" void kernel_launch(void* const* d_in, const int* in_sizes, int n_in,
                              void* d_out, int out_size)
{
    const float* x  = (const float*)d_in[0];
    const float* Wq = (const float*)d_in[1];
    const float* Wk = (const float*)d_in[2];
    const float* Wv = (const float*)d_in[3];
    const float* Wo = (const float*)d_in[4];
    float* y = (float*)d_out;

    const int attn_smem = (64 * KSTR + 128 * VSTR + 128 * PSTR) * (int)sizeof(unsigned);
    const int gemm_smem = (2 * 128 * GSTR) * (int)sizeof(unsigned);
    cudaFuncSetAttribute(attn_kernel, cudaFuncAttributeMaxDynamicSharedMemorySize, attn_smem);
    cudaFuncSetAttribute(qkv_kernel,  cudaFuncAttributeMaxDynamicSharedMemorySize, gemm_smem);
    cudaFuncSetAttribute(wo_kernel,   cudaFuncAttributeMaxDynamicSharedMemorySize, gemm_smem);

    // 1) QKV projections (tf32 tensor)
    {
        dim3 grid((B_ * L_) / 128, (H_ * D_) / 128, 3);
        qkv_kernel<<<grid, 256, gemm_smem>>>(x, Wq, Wk, Wv);
    }
    // 2) Causal flash attention (tf32 tensor)
    {
        dim3 grid(L_ / 128, B_ * H_);
        attn_kernel<<<grid, 256, attn_smem>>>();
    }
    // 3) Output projection (tf32 tensor)
    {
        dim3 grid((B_ * L_) / 128, 1);
        wo_kernel<<<grid, 256, gemm_smem>>>(Wo, y);
    }
}

// round 7
// speedup vs baseline: 2.7783x; 1.1809x over previous
#include <cuda_runtime.h>
#include <math.h>

// Problem constants
#define B_  2
#define L_  4096
#define D_  128
#define H_  4

// Scratch (allocation-free rule: __device__ globals)
__device__ float g_q[B_ * H_ * L_ * D_];
__device__ float g_k[B_ * H_ * L_ * D_];
__device__ float g_v[B_ * H_ * L_ * D_];
__device__ float g_ctx[B_ * L_ * H_ * D_];   // [b][l][h][e]

// ---------------------------------------------------------------------------
// tf32 helpers
// ---------------------------------------------------------------------------
__device__ __forceinline__ unsigned f2tf(float f) {
    unsigned r;
    asm("cvt.rna.tf32.f32 %0, %1;" : "=r"(r) : "f"(f));
    return r;
}

__device__ __forceinline__ void mma8(float d[4], const unsigned a[4],
                                     unsigned b0, unsigned b1) {
    asm volatile(
        "mma.sync.aligned.m16n8k8.row.col.f32.tf32.tf32.f32 "
        "{%0,%1,%2,%3}, {%4,%5,%6,%7}, {%8,%9}, {%0,%1,%2,%3};\n"
        : "+f"(d[0]), "+f"(d[1]), "+f"(d[2]), "+f"(d[3])
        : "r"(a[0]), "r"(a[1]), "r"(a[2]), "r"(a[3]), "r"(b0), "r"(b1));
}

__device__ __forceinline__ void cpa16(unsigned saddr, const void* g) {
    asm volatile("cp.async.cg.shared.global [%0], [%1], 16;"
                 :: "r"(saddr), "l"(g));
}
__device__ __forceinline__ void cpa_commit() {
    asm volatile("cp.async.commit_group;");
}
__device__ __forceinline__ void cpa_wait0() {
    asm volatile("cp.async.wait_group 0;");
}

// pi_128 permutation (qkv staging): element c -> base + {0,8,16,24} within
//   base = (c>>6)*64 + ((c>>2)&1)*32 + ((c>>3)&7)
#define GSTR 132

// ---------------------------------------------------------------------------
// Kernel 1: QKV projections, tf32 tensor cores.  CTA tile 128m x 64n.
// 8 warps = 4m x 2n, warp tile 32m x 32n.  2 CTAs/SM.
// grid = (64, 8, 3).
// ---------------------------------------------------------------------------
__global__ __launch_bounds__(256, 2) void qkv_kernel(
    const float* __restrict__ x,
    const float* __restrict__ Wq,
    const float* __restrict__ Wk,
    const float* __restrict__ Wv)
{
    extern __shared__ unsigned gsm[];
    unsigned* As = gsm;                // 128 * 132
    unsigned* Bs = As + 128 * GSTR;    // 64  * 132

    const float* W   = (blockIdx.z == 0) ? Wq : ((blockIdx.z == 1) ? Wk : Wv);
    float*       out = (blockIdx.z == 0) ? g_q : ((blockIdx.z == 1) ? g_k : g_v);

    const int t    = threadIdx.x;
    const int w    = t >> 5;
    const int lane = t & 31;
    const int rl   = lane >> 2;
    const int cl   = lane & 3;
    const int wm   = w & 3;            // m-warp 0..3 (32 rows)
    const int wn   = w >> 2;           // n-warp 0..1 (32 cols)
    const int m0   = blockIdx.x * 128;
    const int n0   = blockIdx.y * 64;

    // stage X [128x128] pi-permuted
    for (int i = t; i < 4096; i += 256) {
        int row = i >> 5;
        int c4  = (i & 31) * 4;
        int base = row * GSTR + ((c4 >> 6) << 6) + (((c4 >> 2) & 1) << 5) + ((c4 >> 3) & 7);
        float4 xv = *(const float4*)(x + (size_t)(m0 + row) * D_ + c4);
        As[base]      = f2tf(xv.x);
        As[base + 8]  = f2tf(xv.y);
        As[base + 16] = f2tf(xv.z);
        As[base + 24] = f2tf(xv.w);
    }
    // stage W [64x128] pi-permuted
    for (int i = t; i < 2048; i += 256) {
        int row = i >> 5;
        int c4  = (i & 31) * 4;
        int base = row * GSTR + ((c4 >> 6) << 6) + (((c4 >> 2) & 1) << 5) + ((c4 >> 3) & 7);
        float4 wv = *(const float4*)(W + (size_t)(n0 + row) * D_ + c4);
        Bs[base]      = f2tf(wv.x);
        Bs[base + 8]  = f2tf(wv.y);
        Bs[base + 16] = f2tf(wv.z);
        Bs[base + 24] = f2tf(wv.w);
    }
    __syncthreads();

    float acc[2][4][4];
#pragma unroll
    for (int mt = 0; mt < 2; mt++)
#pragma unroll
        for (int nt = 0; nt < 4; nt++)
#pragma unroll
            for (int c = 0; c < 4; c++) acc[mt][nt][c] = 0.f;

#pragma unroll
    for (int ktg = 0; ktg < 4; ktg++) {
        const int kbase = ((ktg >> 1) << 6) + ((ktg & 1) << 2) + cl * 8;
        uint4 a0[2], a1[2], a2[2], a3[2];
#pragma unroll
        for (int mt = 0; mt < 2; mt++) {
            int ar = (wm * 32 + mt * 16 + rl) * GSTR + kbase;
            a0[mt] = *(const uint4*)&As[ar];
            a2[mt] = *(const uint4*)&As[ar + 32];
            a1[mt] = *(const uint4*)&As[ar + 8 * GSTR];
            a3[mt] = *(const uint4*)&As[ar + 8 * GSTR + 32];
        }
#pragma unroll
        for (int nt = 0; nt < 4; nt++) {
            int br = (wn * 32 + nt * 8 + rl) * GSTR + kbase;
            uint4 b0 = *(const uint4*)&Bs[br];
            uint4 b1 = *(const uint4*)&Bs[br + 32];
#pragma unroll
            for (int mt = 0; mt < 2; mt++) {
                unsigned aa[4];
                aa[0] = a0[mt].x; aa[1] = a1[mt].x; aa[2] = a2[mt].x; aa[3] = a3[mt].x;
                mma8(acc[mt][nt], aa, b0.x, b1.x);
                aa[0] = a0[mt].y; aa[1] = a1[mt].y; aa[2] = a2[mt].y; aa[3] = a3[mt].y;
                mma8(acc[mt][nt], aa, b0.y, b1.y);
                aa[0] = a0[mt].z; aa[1] = a1[mt].z; aa[2] = a2[mt].z; aa[3] = a3[mt].z;
                mma8(acc[mt][nt], aa, b0.z, b1.z);
                aa[0] = a0[mt].w; aa[1] = a1[mt].w; aa[2] = a2[mt].w; aa[3] = a3[mt].w;
                mma8(acc[mt][nt], aa, b0.w, b1.w);
            }
        }
    }

    // epilogue: out[b][h][l][e]
    const int h = n0 >> 7;             // 64-col tile never crosses a head
#pragma unroll
    for (int mt = 0; mt < 2; mt++) {
        int m = m0 + wm * 32 + mt * 16 + rl;
        int b = m >> 12;
        int l = m & 4095;
        float* obase = out + (((size_t)b * H_ + h) * L_ + l) * D_;
#pragma unroll
        for (int nt = 0; nt < 4; nt++) {
            int n = n0 + wn * 32 + nt * 8 + 2 * cl;
            int e = n & 127;
            float2 lo; lo.x = acc[mt][nt][0]; lo.y = acc[mt][nt][1];
            float2 hi; hi.x = acc[mt][nt][2]; hi.y = acc[mt][nt][3];
            *(float2*)(obase + e) = lo;
            *(float2*)(obase + 8 * (size_t)D_ + e) = hi;
        }
    }
}

// ---------------------------------------------------------------------------
// Kernel 2: causal flash attention, tf32, cp.async software pipeline.
// grid = (L/128, B*H), block = 256 (8 warps; warp owns 16 q rows).
// smem (words):
//   Kpad[2] : 2 * 64*132 = 16896   (raw fp32 via cp.async; used as truncated tf32)
//   Vraw[2] : 2 * 64*128 = 16384   (raw fp32 via cp.async)
//   Vc      : 64*132     = 8448    (rna tf32, row-major [key][d])
//   Ps      : 128*68     = 8704    (tf32 P, row-major [q][key])
// total 50432 words = 201,728 B
// ---------------------------------------------------------------------------
#define KP_OFF 0
#define VR_OFF 16896
#define VC_OFF 33280
#define PS_OFF 41728
#define SM_WORDS 50432

__global__ __launch_bounds__(256, 1) void attn_kernel()
{
    extern __shared__ unsigned sm[];
    unsigned smem_base = (unsigned)__cvta_generic_to_shared(sm);

    const int t    = threadIdx.x;
    const int w    = t >> 5;
    const int lane = t & 31;
    const int rl   = lane >> 2;
    const int cl   = lane & 3;
    const int qt   = (gridDim.x - 1) - blockIdx.x;   // heavy tiles first
    const int bh   = blockIdx.y;

    const float* qg = g_q + ((size_t)bh * L_ + (size_t)qt * 128) * D_;
    const float* kg = g_k + (size_t)bh * L_ * D_;
    const float* vg = g_v + (size_t)bh * L_ * D_;

    const int ntiles = 2 * qt + 2;

    // ---- issue cp.async for tile 0 into buffer 0 ----
    {
        const float* kp = kg;
        const float* vp = vg;
#pragma unroll
        for (int j = 0; j < 8; j++) {
            int i = t + 256 * j;
            int row = i >> 5;
            int c4  = (i & 31) * 4;
            cpa16(smem_base + (unsigned)(KP_OFF + row * 132 + c4) * 4,
                  kp + (size_t)row * D_ + c4);
            cpa16(smem_base + (unsigned)(VR_OFF + row * 128 + c4) * 4,
                  vp + (size_t)row * D_ + c4);
        }
        cpa_commit();
    }

    // ---- Q A-fragments cached in registers (overlaps with cp.async) ----
    unsigned Qa[16][4];
    {
        const float* qw = qg + (size_t)(w * 16) * D_;
#pragma unroll
        for (int kt = 0; kt < 16; kt++) {
            Qa[kt][0] = f2tf(qw[(size_t)(rl)     * D_ + kt * 8 + cl]);
            Qa[kt][1] = f2tf(qw[(size_t)(rl + 8) * D_ + kt * 8 + cl]);
            Qa[kt][2] = f2tf(qw[(size_t)(rl)     * D_ + kt * 8 + 4 + cl]);
            Qa[kt][3] = f2tf(qw[(size_t)(rl + 8) * D_ + kt * 8 + 4 + cl]);
        }
    }

    float Oacc[16][4];
#pragma unroll
    for (int nt = 0; nt < 16; nt++)
#pragma unroll
        for (int c = 0; c < 4; c++) Oacc[nt][c] = 0.f;
    float m0 = -INFINITY, m1 = -INFINITY, l0 = 0.f, l1 = 0.f;

    const int qg0 = qt * 128 + w * 16 + rl;
    const int qg1 = qg0 + 8;

    unsigned* Ps = sm + PS_OFF;
    unsigned* Vc = sm + VC_OFF;

    int cur = 0;
    for (int kb = 0; kb < ntiles; ++kb, cur ^= 1) {
        cpa_wait0();          // raw[cur] landed (this thread's group)
        __syncthreads();      // everyone's cp.async visible; prev-tile compute done

        const unsigned* Kp = sm + KP_OFF + cur * (64 * 132);
        const float*    Vr = (const float*)(sm + VR_OFF + cur * (64 * 128));

        // ---- convert V raw -> tf32 (rna), row-major, conflict-free ----
#pragma unroll
        for (int j = 0; j < 8; j++) {
            int i = t + 256 * j;
            int row = i >> 5;
            int c4  = (i & 31) * 4;
            float4 v = *(const float4*)(Vr + row * 128 + c4);
            uint4 o;
            o.x = f2tf(v.x); o.y = f2tf(v.y); o.z = f2tf(v.z); o.w = f2tf(v.w);
            *(uint4*)(Vc + row * 132 + c4) = o;
        }
        __syncthreads();      // Vc ready; Vraw[cur] free for reuse as target later

        // ---- issue cp.async for tile kb+1 into buffer cur^1 ----
        if (kb + 1 < ntiles) {
            const float* kp = kg + (size_t)(kb + 1) * 64 * D_;
            const float* vp = vg + (size_t)(kb + 1) * 64 * D_;
            unsigned kb32 = smem_base + (unsigned)(KP_OFF + (cur ^ 1) * (64 * 132)) * 4;
            unsigned vb32 = smem_base + (unsigned)(VR_OFF + (cur ^ 1) * (64 * 128)) * 4;
#pragma unroll
            for (int j = 0; j < 8; j++) {
                int i = t + 256 * j;
                int row = i >> 5;
                int c4  = (i & 31) * 4;
                cpa16(kb32 + (unsigned)(row * 132 + c4) * 4, kp + (size_t)row * D_ + c4);
                cpa16(vb32 + (unsigned)(row * 128 + c4) * 4, vp + (size_t)row * D_ + c4);
            }
            cpa_commit();
        }

        // ---- S = Q K^T  (K raw fp32 bits used as truncated tf32) ----
        float Sf[8][4];
#pragma unroll
        for (int nt = 0; nt < 8; nt++)
#pragma unroll
            for (int c = 0; c < 4; c++) Sf[nt][c] = 0.f;

#pragma unroll
        for (int kt = 0; kt < 16; kt++) {
#pragma unroll
            for (int nt = 0; nt < 8; nt++) {
                unsigned b0 = Kp[(nt * 8 + rl) * 132 + kt * 8 + cl];
                unsigned b1 = Kp[(nt * 8 + rl) * 132 + kt * 8 + 4 + cl];
                mma8(Sf[nt], Qa[kt], b0, b1);
            }
        }

        // ---- causal mask (diagonal tiles only) ----
        if (kb >= 2 * qt) {
#pragma unroll
            for (int nt = 0; nt < 8; nt++) {
                int kgb = kb * 64 + nt * 8 + 2 * cl;
                if (kgb     > qg0) Sf[nt][0] = -INFINITY;
                if (kgb + 1 > qg0) Sf[nt][1] = -INFINITY;
                if (kgb     > qg1) Sf[nt][2] = -INFINITY;
                if (kgb + 1 > qg1) Sf[nt][3] = -INFINITY;
            }
        }

        // ---- online softmax; P stored row-major [q][key] ----
        float mx0 = Sf[0][0], mx1 = Sf[0][2];
#pragma unroll
        for (int nt = 0; nt < 8; nt++) {
            mx0 = fmaxf(mx0, fmaxf(Sf[nt][0], Sf[nt][1]));
            mx1 = fmaxf(mx1, fmaxf(Sf[nt][2], Sf[nt][3]));
        }
        mx0 = fmaxf(mx0, __shfl_xor_sync(0xffffffffu, mx0, 1));
        mx0 = fmaxf(mx0, __shfl_xor_sync(0xffffffffu, mx0, 2));
        mx1 = fmaxf(mx1, __shfl_xor_sync(0xffffffffu, mx1, 1));
        mx1 = fmaxf(mx1, __shfl_xor_sync(0xffffffffu, mx1, 2));

        float mn0 = fmaxf(m0, mx0);
        float mn1 = fmaxf(m1, mx1);
        float sc0 = __expf(m0 - mn0);
        float sc1 = __expf(m1 - mn1);
        m0 = mn0; m1 = mn1;

        float rs0 = 0.f, rs1 = 0.f;
        unsigned* prow0 = Ps + (w * 16 + rl)     * 68 + 2 * cl;
        unsigned* prow1 = Ps + (w * 16 + 8 + rl) * 68 + 2 * cl;
#pragma unroll
        for (int nt = 0; nt < 8; nt++) {
            float p0 = __expf(Sf[nt][0] - mn0);
            float p1 = __expf(Sf[nt][1] - mn0);
            float p2 = __expf(Sf[nt][2] - mn1);
            float p3 = __expf(Sf[nt][3] - mn1);
            rs0 += p0 + p1;
            rs1 += p2 + p3;
            uint2 s0; s0.x = f2tf(p0); s0.y = f2tf(p1);
            uint2 s1; s1.x = f2tf(p2); s1.y = f2tf(p3);
            *(uint2*)(prow0 + nt * 8) = s0;
            *(uint2*)(prow1 + nt * 8) = s1;
        }
        rs0 += __shfl_xor_sync(0xffffffffu, rs0, 1);
        rs0 += __shfl_xor_sync(0xffffffffu, rs0, 2);
        rs1 += __shfl_xor_sync(0xffffffffu, rs1, 1);
        rs1 += __shfl_xor_sync(0xffffffffu, rs1, 2);
        l0 = l0 * sc0 + rs0;
        l1 = l1 * sc1 + rs1;

#pragma unroll
        for (int nt = 0; nt < 16; nt++) {
            Oacc[nt][0] *= sc0; Oacc[nt][1] *= sc0;
            Oacc[nt][2] *= sc1; Oacc[nt][3] *= sc1;
        }
        __syncwarp();   // Ps rows are warp-private

        // ---- O += P V  (V row-major [key][d], B-frag 2-way worst case) ----
#pragma unroll
        for (int kt = 0; kt < 8; kt++) {
            unsigned Pa[4];
            Pa[0] = Ps[(w * 16 + rl)     * 68 + kt * 8 + cl];
            Pa[1] = Ps[(w * 16 + 8 + rl) * 68 + kt * 8 + cl];
            Pa[2] = Ps[(w * 16 + rl)     * 68 + kt * 8 + 4 + cl];
            Pa[3] = Ps[(w * 16 + 8 + rl) * 68 + kt * 8 + 4 + cl];
#pragma unroll
            for (int nt = 0; nt < 16; nt++) {
                unsigned b0 = Vc[(kt * 8 + cl)     * 132 + nt * 8 + rl];
                unsigned b1 = Vc[(kt * 8 + 4 + cl) * 132 + nt * 8 + rl];
                mma8(Oacc[nt], Pa, b0, b1);
            }
        }
    }

    // ---- epilogue: normalize, write ctx[b][l][h][e] ----
    float inv0 = 1.f / l0;
    float inv1 = 1.f / l1;
    const int b = bh >> 2;
    const int h = bh & 3;
    float* dst0 = g_ctx + ((size_t)(b * L_ + qt * 128 + w * 16 + rl))     * (H_ * D_) + h * D_ + 2 * cl;
    float* dst1 = g_ctx + ((size_t)(b * L_ + qt * 128 + w * 16 + 8 + rl)) * (H_ * D_) + h * D_ + 2 * cl;
#pragma unroll
    for (int nt = 0; nt < 16; nt++) {
        float2 o0; o0.x = Oacc[nt][0] * inv0; o0.y = Oacc[nt][1] * inv0;
        float2 o1; o1.x = Oacc[nt][2] * inv1; o1.y = Oacc[nt][3] * inv1;
        *(float2*)(dst0 + nt * 8) = o0;
        *(float2*)(dst1 + nt * 8) = o1;
    }
}

// ---------------------------------------------------------------------------
// Kernel 3: output projection, tf32 tensor cores (unchanged).
// y[8192,128] = CTX[8192,512] @ Wo^T.  grid = (64).
// ---------------------------------------------------------------------------
__global__ __launch_bounds__(256) void wo_kernel(
    const float* __restrict__ Wo,
    float* __restrict__ y)
{
    extern __shared__ unsigned gsm[];
    unsigned* As = gsm;
    unsigned* Bs = As + 128 * GSTR;

    const int t    = threadIdx.x;
    const int w    = t >> 5;
    const int lane = t & 31;
    const int rl   = lane >> 2;
    const int cl   = lane & 3;
    const int wm   = w & 3;
    const int wn   = w >> 2;
    const int m0   = blockIdx.x * 128;

    float acc[2][8][4];
#pragma unroll
    for (int mt = 0; mt < 2; mt++)
#pragma unroll
        for (int nt = 0; nt < 8; nt++)
#pragma unroll
            for (int c = 0; c < 4; c++) acc[mt][nt][c] = 0.f;

    for (int kc = 0; kc < H_ * D_; kc += 128) {
        __syncthreads();
        for (int i = t; i < 4096; i += 256) {
            int row = i >> 5;
            int c4  = (i & 31) * 4;
            int base = row * GSTR + ((c4 >> 6) << 6) + (((c4 >> 2) & 1) << 5) + ((c4 >> 3) & 7);
            float4 av = *(const float4*)(g_ctx + (size_t)(m0 + row) * (H_ * D_) + kc + c4);
            As[base]      = f2tf(av.x);
            As[base + 8]  = f2tf(av.y);
            As[base + 16] = f2tf(av.z);
            As[base + 24] = f2tf(av.w);
            float4 wv = *(const float4*)(Wo + (size_t)row * (H_ * D_) + kc + c4);
            Bs[base]      = f2tf(wv.x);
            Bs[base + 8]  = f2tf(wv.y);
            Bs[base + 16] = f2tf(wv.z);
            Bs[base + 24] = f2tf(wv.w);
        }
        __syncthreads();

#pragma unroll
        for (int ktg = 0; ktg < 4; ktg++) {
            const int kbase = ((ktg >> 1) << 6) + ((ktg & 1) << 2) + cl * 8;
            uint4 a0[2], a1[2], a2[2], a3[2];
#pragma unroll
            for (int mt = 0; mt < 2; mt++) {
                int ar = (wm * 32 + mt * 16 + rl) * GSTR + kbase;
                a0[mt] = *(const uint4*)&As[ar];
                a2[mt] = *(const uint4*)&As[ar + 32];
                a1[mt] = *(const uint4*)&As[ar + 8 * GSTR];
                a3[mt] = *(const uint4*)&As[ar + 8 * GSTR + 32];
            }
#pragma unroll
            for (int nt = 0; nt < 8; nt++) {
                int br = (wn * 64 + nt * 8 + rl) * GSTR + kbase;
                uint4 b0 = *(const uint4*)&Bs[br];
                uint4 b1 = *(const uint4*)&Bs[br + 32];
#pragma unroll
                for (int mt = 0; mt < 2; mt++) {
                    unsigned aa[4];
                    aa[0] = a0[mt].x; aa[1] = a1[mt].x; aa[2] = a2[mt].x; aa[3] = a3[mt].x;
                    mma8(acc[mt][nt], aa, b0.x, b1.x);
                    aa[0] = a0[mt].y; aa[1] = a1[mt].y; aa[2] = a2[mt].y; aa[3] = a3[mt].y;
                    mma8(acc[mt][nt], aa, b0.y, b1.y);
                    aa[0] = a0[mt].z; aa[1] = a1[mt].z; aa[2] = a2[mt].z; aa[3] = a3[mt].z;
                    mma8(acc[mt][nt], aa, b0.z, b1.z);
                    aa[0] = a0[mt].w; aa[1] = a1[mt].w; aa[2] = a2[mt].w; aa[3] = a3[mt].w;
                    mma8(acc[mt][nt], aa, b0.w, b1.w);
                }
            }
        }
    }

#pragma unroll
    for (int mt = 0; mt < 2; mt++) {
        int m = m0 + wm * 32 + mt * 16 + rl;
#pragma unroll
        for (int nt = 0; nt < 8; nt++) {
            int n = wn * 64 + nt * 8 + 2 * cl;
            float* dst = y + (size_t)m * D_ + n;
            float2 lo; lo.x = acc[mt][nt][0]; lo.y = acc[mt][nt][1];
            float2 hi; hi.x = acc[mt][nt][2]; hi.y = acc[mt][nt][3];
            *(float2*)dst = lo;
            *(float2*)(dst + 8 * (size_t)D_) = hi;
        }
    }
}

// ---------------------------------------------------------------------------
extern "C" void kernel_launch(void* const* d_in, const int* in_sizes, int n_in,
                              void* d_out, int out_size)
{
    const float* x  = (const float*)d_in[0];
    const float* Wq = (const float*)d_in[1];
    const float* Wk = (const float*)d_in[2];
    const float* Wv = (const float*)d_in[3];
    const float* Wo = (const float*)d_in[4];
    float* y = (float*)d_out;

    const int attn_smem = SM_WORDS * (int)sizeof(unsigned);               // 201,728 B
    const int qkv_smem  = (128 * GSTR + 64 * GSTR) * (int)sizeof(unsigned); // 101,376 B
    const int wo_smem   = (2 * 128 * GSTR) * (int)sizeof(unsigned);       // 135,168 B
    cudaFuncSetAttribute(attn_kernel, cudaFuncAttributeMaxDynamicSharedMemorySize, attn_smem);
    cudaFuncSetAttribute(qkv_kernel,  cudaFuncAttributeMaxDynamicSharedMemorySize, qkv_smem);
    cudaFuncSetAttribute(wo_kernel,   cudaFuncAttributeMaxDynamicSharedMemorySize, wo_smem);

    // 1) QKV projections (tf32 tensor, 2 CTAs/SM)
    {
        dim3 grid((B_ * L_) / 128, (H_ * D_) / 64, 3);
        qkv_kernel<<<grid, 256, qkv_smem>>>(x, Wq, Wk, Wv);
    }
    // 2) Causal flash attention (tf32 tensor, cp.async pipeline)
    {
        dim3 grid(L_ / 128, B_ * H_);
        attn_kernel<<<grid, 256, attn_smem>>>();
    }
    // 3) Output projection (tf32 tensor)
    {
        dim3 grid((B_ * L_) / 128, 1);
        wo_kernel<<<grid, 256, wo_smem>>>(Wo, y);
    }
}

// round 10
// speedup vs baseline: 2.8797x; 1.0365x over previous
#include <cuda_runtime.h>
#include <math.h>

// Problem constants
#define B_  2
#define L_  4096
#define D_  128
#define H_  4

// Scratch (allocation-free rule: __device__ globals)
__device__ float g_q[B_ * H_ * L_ * D_];
__device__ float g_k[B_ * H_ * L_ * D_];
__device__ float g_v[B_ * H_ * L_ * D_];
__device__ float g_ctx[B_ * L_ * H_ * D_];   // [b][l][h][e]

// ---------------------------------------------------------------------------
// tf32 helpers
// ---------------------------------------------------------------------------
__device__ __forceinline__ unsigned f2tf(float f) {
    unsigned r;
    asm("cvt.rna.tf32.f32 %0, %1;" : "=r"(r) : "f"(f));
    return r;
}

__device__ __forceinline__ void mma8(float d[4], const unsigned a[4],
                                     unsigned b0, unsigned b1) {
    asm volatile(
        "mma.sync.aligned.m16n8k8.row.col.f32.tf32.tf32.f32 "
        "{%0,%1,%2,%3}, {%4,%5,%6,%7}, {%8,%9}, {%0,%1,%2,%3};\n"
        : "+f"(d[0]), "+f"(d[1]), "+f"(d[2]), "+f"(d[3])
        : "r"(a[0]), "r"(a[1]), "r"(a[2]), "r"(a[3]), "r"(b0), "r"(b1));
}

__device__ __forceinline__ void cpa16(unsigned saddr, const void* g) {
    asm volatile("cp.async.cg.shared.global [%0], [%1], 16;"
                 :: "r"(saddr), "l"(g));
}
__device__ __forceinline__ void cpa_commit() {
    asm volatile("cp.async.commit_group;");
}
__device__ __forceinline__ void cpa_wait0() {
    asm volatile("cp.async.wait_group 0;");
}

// pi_128 permutation (GEMM staging): element c -> base + {0,8,16,24} within
//   base = (c>>6)*64 + ((c>>2)&1)*32 + ((c>>3)&7)
#define GSTR 132

// ---------------------------------------------------------------------------
// Kernel 1: QKV projections, tf32 tensor cores.  CTA tile 128m x 64n.
// 8 warps = 4m x 2n, warp tile 32m x 32n.  2 CTAs/SM.  grid = (64, 8, 3).
// ---------------------------------------------------------------------------
__global__ __launch_bounds__(256, 2) void qkv_kernel(
    const float* __restrict__ x,
    const float* __restrict__ Wq,
    const float* __restrict__ Wk,
    const float* __restrict__ Wv)
{
    extern __shared__ unsigned gsm[];
    unsigned* As = gsm;                // 128 * 132
    unsigned* Bs = As + 128 * GSTR;    // 64  * 132

    const float* W   = (blockIdx.z == 0) ? Wq : ((blockIdx.z == 1) ? Wk : Wv);
    float*       out = (blockIdx.z == 0) ? g_q : ((blockIdx.z == 1) ? g_k : g_v);

    const int t    = threadIdx.x;
    const int w    = t >> 5;
    const int lane = t & 31;
    const int rl   = lane >> 2;
    const int cl   = lane & 3;
    const int wm   = w & 3;
    const int wn   = w >> 2;
    const int m0   = blockIdx.x * 128;
    const int n0   = blockIdx.y * 64;

    for (int i = t; i < 4096; i += 256) {
        int row = i >> 5;
        int c4  = (i & 31) * 4;
        int base = row * GSTR + ((c4 >> 6) << 6) + (((c4 >> 2) & 1) << 5) + ((c4 >> 3) & 7);
        float4 xv = *(const float4*)(x + (size_t)(m0 + row) * D_ + c4);
        As[base]      = f2tf(xv.x);
        As[base + 8]  = f2tf(xv.y);
        As[base + 16] = f2tf(xv.z);
        As[base + 24] = f2tf(xv.w);
    }
    for (int i = t; i < 2048; i += 256) {
        int row = i >> 5;
        int c4  = (i & 31) * 4;
        int base = row * GSTR + ((c4 >> 6) << 6) + (((c4 >> 2) & 1) << 5) + ((c4 >> 3) & 7);
        float4 wv = *(const float4*)(W + (size_t)(n0 + row) * D_ + c4);
        Bs[base]      = f2tf(wv.x);
        Bs[base + 8]  = f2tf(wv.y);
        Bs[base + 16] = f2tf(wv.z);
        Bs[base + 24] = f2tf(wv.w);
    }
    __syncthreads();

    float acc[2][4][4];
#pragma unroll
    for (int mt = 0; mt < 2; mt++)
#pragma unroll
        for (int nt = 0; nt < 4; nt++)
#pragma unroll
            for (int c = 0; c < 4; c++) acc[mt][nt][c] = 0.f;

#pragma unroll
    for (int ktg = 0; ktg < 4; ktg++) {
        const int kbase = ((ktg >> 1) << 6) + ((ktg & 1) << 2) + cl * 8;
        uint4 a0[2], a1[2], a2[2], a3[2];
#pragma unroll
        for (int mt = 0; mt < 2; mt++) {
            int ar = (wm * 32 + mt * 16 + rl) * GSTR + kbase;
            a0[mt] = *(const uint4*)&As[ar];
            a2[mt] = *(const uint4*)&As[ar + 32];
            a1[mt] = *(const uint4*)&As[ar + 8 * GSTR];
            a3[mt] = *(const uint4*)&As[ar + 8 * GSTR + 32];
        }
#pragma unroll
        for (int nt = 0; nt < 4; nt++) {
            int br = (wn * 32 + nt * 8 + rl) * GSTR + kbase;
            uint4 b0 = *(const uint4*)&Bs[br];
            uint4 b1 = *(const uint4*)&Bs[br + 32];
#pragma unroll
            for (int mt = 0; mt < 2; mt++) {
                unsigned aa[4];
                aa[0] = a0[mt].x; aa[1] = a1[mt].x; aa[2] = a2[mt].x; aa[3] = a3[mt].x;
                mma8(acc[mt][nt], aa, b0.x, b1.x);
                aa[0] = a0[mt].y; aa[1] = a1[mt].y; aa[2] = a2[mt].y; aa[3] = a3[mt].y;
                mma8(acc[mt][nt], aa, b0.y, b1.y);
                aa[0] = a0[mt].z; aa[1] = a1[mt].z; aa[2] = a2[mt].z; aa[3] = a3[mt].z;
                mma8(acc[mt][nt], aa, b0.z, b1.z);
                aa[0] = a0[mt].w; aa[1] = a1[mt].w; aa[2] = a2[mt].w; aa[3] = a3[mt].w;
                mma8(acc[mt][nt], aa, b0.w, b1.w);
            }
        }
    }

    const int h = n0 >> 7;
#pragma unroll
    for (int mt = 0; mt < 2; mt++) {
        int m = m0 + wm * 32 + mt * 16 + rl;
        int b = m >> 12;
        int l = m & 4095;
        float* obase = out + (((size_t)b * H_ + h) * L_ + l) * D_;
#pragma unroll
        for (int nt = 0; nt < 4; nt++) {
            int n = n0 + wn * 32 + nt * 8 + 2 * cl;
            int e = n & 127;
            float2 lo; lo.x = acc[mt][nt][0]; lo.y = acc[mt][nt][1];
            float2 hi; hi.x = acc[mt][nt][2]; hi.y = acc[mt][nt][3];
            *(float2*)(obase + e) = lo;
            *(float2*)(obase + 8 * (size_t)D_ + e) = hi;
        }
    }
}

// ---------------------------------------------------------------------------
// Kernel 2: causal flash attention, tf32, cp.async pipeline, 1 barrier/tile.
// grid = (L/128, B*H), block = 256 (8 warps; warp owns 16 q rows).
// smem (words), all K/V rows at stride 136 (conflict-free fragment reads):
//   Kraw[2] : 2*64*136 = 17408  (raw fp32 -> used as truncated tf32)
//   Vraw[2] : 2*64*136 = 17408  (raw fp32 -> rna cvt inline in registers)
//   Ps      : 128*68   = 8704   (tf32 P, row-major [q][key])
// total 43520 words = 174,080 B
// ---------------------------------------------------------------------------
#define KSTRW 136
#define KP_OFF 0
#define VR_OFF (2 * 64 * KSTRW)
#define PS_OFF (VR_OFF + 2 * 64 * KSTRW)
#define SM_WORDS (PS_OFF + 128 * 68)

__global__ __launch_bounds__(256, 1) void attn_kernel()
{
    extern __shared__ unsigned sm[];
    unsigned smem_base = (unsigned)__cvta_generic_to_shared(sm);

    const int t    = threadIdx.x;
    const int w    = t >> 5;
    const int lane = t & 31;
    const int rl   = lane >> 2;
    const int cl   = lane & 3;
    const int qt   = (gridDim.x - 1) - blockIdx.x;   // heavy tiles first
    const int bh   = blockIdx.y;

    const float* qg = g_q + ((size_t)bh * L_ + (size_t)qt * 128) * D_;
    const float* kg = g_k + (size_t)bh * L_ * D_;
    const float* vg = g_v + (size_t)bh * L_ * D_;

    const int ntiles = 2 * qt + 2;

    // ---- issue cp.async for tile 0 into buffer 0 ----
    {
#pragma unroll
        for (int j = 0; j < 8; j++) {
            int i = t + 256 * j;
            int row = i >> 5;
            int c4  = (i & 31) * 4;
            cpa16(smem_base + (unsigned)(KP_OFF + row * KSTRW + c4) * 4,
                  kg + (size_t)row * D_ + c4);
            cpa16(smem_base + (unsigned)(VR_OFF + row * KSTRW + c4) * 4,
                  vg + (size_t)row * D_ + c4);
        }
        cpa_commit();
    }

    // ---- Q A-fragments cached in registers (overlaps with cp.async) ----
    unsigned Qa[16][4];
    {
        const float* qw = qg + (size_t)(w * 16) * D_;
#pragma unroll
        for (int kt = 0; kt < 16; kt++) {
            Qa[kt][0] = f2tf(qw[(size_t)(rl)     * D_ + kt * 8 + cl]);
            Qa[kt][1] = f2tf(qw[(size_t)(rl + 8) * D_ + kt * 8 + cl]);
            Qa[kt][2] = f2tf(qw[(size_t)(rl)     * D_ + kt * 8 + 4 + cl]);
            Qa[kt][3] = f2tf(qw[(size_t)(rl + 8) * D_ + kt * 8 + 4 + cl]);
        }
    }

    float Oacc[16][4];
#pragma unroll
    for (int nt = 0; nt < 16; nt++)
#pragma unroll
        for (int c = 0; c < 4; c++) Oacc[nt][c] = 0.f;
    float m0 = -INFINITY, m1 = -INFINITY, l0 = 0.f, l1 = 0.f;

    const int qg0 = qt * 128 + w * 16 + rl;
    const int qg1 = qg0 + 8;

    unsigned* Ps = sm + PS_OFF;

    int cur = 0;
    for (int kb = 0; kb < ntiles; ++kb, cur ^= 1) {
        cpa_wait0();          // this thread's tile-kb groups landed
        __syncthreads();      // all threads' cp.async visible; prev compute done

        const unsigned* Kp = sm + KP_OFF + cur * (64 * KSTRW);
        const float*    Vr = (const float*)(sm + VR_OFF + cur * (64 * KSTRW));

        // ---- issue cp.async for tile kb+1 into buffer cur^1 ----
        if (kb + 1 < ntiles) {
            const float* kp = kg + (size_t)(kb + 1) * 64 * D_;
            const float* vp = vg + (size_t)(kb + 1) * 64 * D_;
            unsigned kb32 = smem_base + (unsigned)(KP_OFF + (cur ^ 1) * (64 * KSTRW)) * 4;
            unsigned vb32 = smem_base + (unsigned)(VR_OFF + (cur ^ 1) * (64 * KSTRW)) * 4;
#pragma unroll
            for (int j = 0; j < 8; j++) {
                int i = t + 256 * j;
                int row = i >> 5;
                int c4  = (i & 31) * 4;
                cpa16(kb32 + (unsigned)(row * KSTRW + c4) * 4, kp + (size_t)row * D_ + c4);
                cpa16(vb32 + (unsigned)(row * KSTRW + c4) * 4, vp + (size_t)row * D_ + c4);
            }
            cpa_commit();
        }

        // ---- S = Q K^T  (K raw fp32 bits used as truncated tf32) ----
        float Sf[8][4];
#pragma unroll
        for (int nt = 0; nt < 8; nt++)
#pragma unroll
            for (int c = 0; c < 4; c++) Sf[nt][c] = 0.f;

#pragma unroll
        for (int kt = 0; kt < 16; kt++) {
#pragma unroll
            for (int nt = 0; nt < 8; nt++) {
                unsigned b0 = Kp[(nt * 8 + rl) * KSTRW + kt * 8 + cl];
                unsigned b1 = Kp[(nt * 8 + rl) * KSTRW + kt * 8 + 4 + cl];
                mma8(Sf[nt], Qa[kt], b0, b1);
            }
        }

        // ---- causal mask (diagonal tiles only) ----
        if (kb >= 2 * qt) {
#pragma unroll
            for (int nt = 0; nt < 8; nt++) {
                int kgb = kb * 64 + nt * 8 + 2 * cl;
                if (kgb     > qg0) Sf[nt][0] = -INFINITY;
                if (kgb + 1 > qg0) Sf[nt][1] = -INFINITY;
                if (kgb     > qg1) Sf[nt][2] = -INFINITY;
                if (kgb + 1 > qg1) Sf[nt][3] = -INFINITY;
            }
        }

        // ---- online softmax; P stored row-major [q][key] (warp-private rows) ----
        float mx0 = Sf[0][0], mx1 = Sf[0][2];
#pragma unroll
        for (int nt = 0; nt < 8; nt++) {
            mx0 = fmaxf(mx0, fmaxf(Sf[nt][0], Sf[nt][1]));
            mx1 = fmaxf(mx1, fmaxf(Sf[nt][2], Sf[nt][3]));
        }
        mx0 = fmaxf(mx0, __shfl_xor_sync(0xffffffffu, mx0, 1));
        mx0 = fmaxf(mx0, __shfl_xor_sync(0xffffffffu, mx0, 2));
        mx1 = fmaxf(mx1, __shfl_xor_sync(0xffffffffu, mx1, 1));
        mx1 = fmaxf(mx1, __shfl_xor_sync(0xffffffffu, mx1, 2));

        float mn0 = fmaxf(m0, mx0);
        float mn1 = fmaxf(m1, mx1);
        float sc0 = __expf(m0 - mn0);
        float sc1 = __expf(m1 - mn1);
        m0 = mn0; m1 = mn1;

        float rs0 = 0.f, rs1 = 0.f;
        unsigned* prow0 = Ps + (w * 16 + rl)     * 68 + 2 * cl;
        unsigned* prow1 = Ps + (w * 16 + 8 + rl) * 68 + 2 * cl;
#pragma unroll
        for (int nt = 0; nt < 8; nt++) {
            float p0 = __expf(Sf[nt][0] - mn0);
            float p1 = __expf(Sf[nt][1] - mn0);
            float p2 = __expf(Sf[nt][2] - mn1);
            float p3 = __expf(Sf[nt][3] - mn1);
            rs0 += p0 + p1;
            rs1 += p2 + p3;
            uint2 s0; s0.x = f2tf(p0); s0.y = f2tf(p1);
            uint2 s1; s1.x = f2tf(p2); s1.y = f2tf(p3);
            *(uint2*)(prow0 + nt * 8) = s0;
            *(uint2*)(prow1 + nt * 8) = s1;
        }
        rs0 += __shfl_xor_sync(0xffffffffu, rs0, 1);
        rs0 += __shfl_xor_sync(0xffffffffu, rs0, 2);
        rs1 += __shfl_xor_sync(0xffffffffu, rs1, 1);
        rs1 += __shfl_xor_sync(0xffffffffu, rs1, 2);
        l0 = l0 * sc0 + rs0;
        l1 = l1 * sc1 + rs1;

#pragma unroll
        for (int nt = 0; nt < 16; nt++) {
            Oacc[nt][0] *= sc0; Oacc[nt][1] *= sc0;
            Oacc[nt][2] *= sc1; Oacc[nt][3] *= sc1;
        }
        __syncwarp();   // Ps rows are warp-private

        // ---- O += P V  (V raw, rna-converted inline; conflict-free stride 136) ----
#pragma unroll
        for (int kt = 0; kt < 8; kt++) {
            unsigned Pa[4];
            Pa[0] = Ps[(w * 16 + rl)     * 68 + kt * 8 + cl];
            Pa[1] = Ps[(w * 16 + 8 + rl) * 68 + kt * 8 + cl];
            Pa[2] = Ps[(w * 16 + rl)     * 68 + kt * 8 + 4 + cl];
            Pa[3] = Ps[(w * 16 + 8 + rl) * 68 + kt * 8 + 4 + cl];
#pragma unroll
            for (int nt = 0; nt < 16; nt++) {
                float v0 = Vr[(kt * 8 + cl)     * KSTRW + nt * 8 + rl];
                float v1 = Vr[(kt * 8 + 4 + cl) * KSTRW + nt * 8 + rl];
                mma8(Oacc[nt], Pa, f2tf(v0), f2tf(v1));
            }
        }
    }

    // ---- epilogue: normalize, write ctx[b][l][h][e] ----
    float inv0 = 1.f / l0;
    float inv1 = 1.f / l1;
    const int b = bh >> 2;
    const int h = bh & 3;
    float* dst0 = g_ctx + ((size_t)(b * L_ + qt * 128 + w * 16 + rl))     * (H_ * D_) + h * D_ + 2 * cl;
    float* dst1 = g_ctx + ((size_t)(b * L_ + qt * 128 + w * 16 + 8 + rl)) * (H_ * D_) + h * D_ + 2 * cl;
#pragma unroll
    for (int nt = 0; nt < 16; nt++) {
        float2 o0; o0.x = Oacc[nt][0] * inv0; o0.y = Oacc[nt][1] * inv0;
        float2 o1; o1.x = Oacc[nt][2] * inv1; o1.y = Oacc[nt][3] * inv1;
        *(float2*)(dst0 + nt * 8) = o0;
        *(float2*)(dst1 + nt * 8) = o1;
    }
}

// ---------------------------------------------------------------------------
// Kernel 3: output projection, tf32 tensor cores.  CTA tile 64m x 64n.
// grid = (128, 2) = 256 CTAs; 2 CTAs/SM.  8 warps = 4m x 2n, warp 16m x 32n.
// ---------------------------------------------------------------------------
__global__ __launch_bounds__(256, 2) void wo_kernel(
    const float* __restrict__ Wo,
    float* __restrict__ y)
{
    extern __shared__ unsigned gsm[];
    unsigned* As = gsm;               // 64 * 132
    unsigned* Bs = As + 64 * GSTR;    // 64 * 132

    const int t    = threadIdx.x;
    const int w    = t >> 5;
    const int lane = t & 31;
    const int rl   = lane >> 2;
    const int cl   = lane & 3;
    const int wm   = w & 3;
    const int wn   = w >> 2;
    const int m0   = blockIdx.x * 64;
    const int n0   = blockIdx.y * 64;

    float acc[4][4];
#pragma unroll
    for (int nt = 0; nt < 4; nt++)
#pragma unroll
        for (int c = 0; c < 4; c++) acc[nt][c] = 0.f;

    for (int kc = 0; kc < H_ * D_; kc += 128) {
        __syncthreads();
        for (int i = t; i < 2048; i += 256) {
            int row = i >> 5;
            int c4  = (i & 31) * 4;
            int base = row * GSTR + ((c4 >> 6) << 6) + (((c4 >> 2) & 1) << 5) + ((c4 >> 3) & 7);
            float4 av = *(const float4*)(g_ctx + (size_t)(m0 + row) * (H_ * D_) + kc + c4);
            As[base]      = f2tf(av.x);
            As[base + 8]  = f2tf(av.y);
            As[base + 16] = f2tf(av.z);
            As[base + 24] = f2tf(av.w);
            float4 wv = *(const float4*)(Wo + (size_t)(n0 + row) * (H_ * D_) + kc + c4);
            Bs[base]      = f2tf(wv.x);
            Bs[base + 8]  = f2tf(wv.y);
            Bs[base + 16] = f2tf(wv.z);
            Bs[base + 24] = f2tf(wv.w);
        }
        __syncthreads();

#pragma unroll
        for (int ktg = 0; ktg < 4; ktg++) {
            const int kbase = ((ktg >> 1) << 6) + ((ktg & 1) << 2) + cl * 8;
            int ar = (wm * 16 + rl) * GSTR + kbase;
            uint4 a0 = *(const uint4*)&As[ar];
            uint4 a2 = *(const uint4*)&As[ar + 32];
            uint4 a1 = *(const uint4*)&As[ar + 8 * GSTR];
            uint4 a3 = *(const uint4*)&As[ar + 8 * GSTR + 32];
#pragma unroll
            for (int nt = 0; nt < 4; nt++) {
                int br = (wn * 32 + nt * 8 + rl) * GSTR + kbase;
                uint4 b0 = *(const uint4*)&Bs[br];
                uint4 b1 = *(const uint4*)&Bs[br + 32];
                unsigned aa[4];
                aa[0] = a0.x; aa[1] = a1.x; aa[2] = a2.x; aa[3] = a3.x;
                mma8(acc[nt], aa, b0.x, b1.x);
                aa[0] = a0.y; aa[1] = a1.y; aa[2] = a2.y; aa[3] = a3.y;
                mma8(acc[nt], aa, b0.y, b1.y);
                aa[0] = a0.z; aa[1] = a1.z; aa[2] = a2.z; aa[3] = a3.z;
                mma8(acc[nt], aa, b0.z, b1.z);
                aa[0] = a0.w; aa[1] = a1.w; aa[2] = a2.w; aa[3] = a3.w;
                mma8(acc[nt], aa, b0.w, b1.w);
            }
        }
    }

    int m = m0 + wm * 16 + rl;
#pragma unroll
    for (int nt = 0; nt < 4; nt++) {
        int n = n0 + wn * 32 + nt * 8 + 2 * cl;
        float2 lo; lo.x = acc[nt][0]; lo.y = acc[nt][1];
        float2 hi; hi.x = acc[nt][2]; hi.y = acc[nt][3];
        *(float2*)(y + (size_t)m * D_ + n) = lo;
        *(float2*)(y + (size_t)(m + 8) * D_ + n) = hi;
    }
}

// ---------------------------------------------------------------------------
extern "C" void kernel_launch(void* const* d_in, const int* in_sizes, int n_in,
                              void* d_out, int out_size)
{
    const float* x  = (const float*)d_in[0];
    const float* Wq = (const float*)d_in[1];
    const float* Wk = (const float*)d_in[2];
    const float* Wv = (const float*)d_in[3];
    const float* Wo = (const float*)d_in[4];
    float* y = (float*)d_out;

    const int attn_smem = SM_WORDS * (int)sizeof(unsigned);                  // 174,080 B
    const int qkv_smem  = (128 * GSTR + 64 * GSTR) * (int)sizeof(unsigned);  // 101,376 B
    const int wo_smem   = (2 * 64 * GSTR) * (int)sizeof(unsigned);           // 67,584 B
    cudaFuncSetAttribute(attn_kernel, cudaFuncAttributeMaxDynamicSharedMemorySize, attn_smem);
    cudaFuncSetAttribute(qkv_kernel,  cudaFuncAttributeMaxDynamicSharedMemorySize, qkv_smem);
    cudaFuncSetAttribute(wo_kernel,   cudaFuncAttributeMaxDynamicSharedMemorySize, wo_smem);

    // 1) QKV projections (tf32 tensor, 2 CTAs/SM)
    {
        dim3 grid((B_ * L_) / 128, (H_ * D_) / 64, 3);
        qkv_kernel<<<grid, 256, qkv_smem>>>(x, Wq, Wk, Wv);
    }
    // 2) Causal flash attention (tf32 tensor, cp.async pipeline, 1 bar/tile)
    {
        dim3 grid(L_ / 128, B_ * H_);
        attn_kernel<<<grid, 256, attn_smem>>>();
    }
    // 3) Output projection (tf32 tensor, 256 CTAs)
    {
        dim3 grid((B_ * L_) / 64, D_ / 64);
        wo_kernel<<<grid, 256, wo_smem>>>(Wo, y);
    }
}